// round 1
// baseline (speedup 1.0000x reference)
#include <cuda_runtime.h>
#include <math.h>

#define T_TOKENS 8192
#define DM 1024
#define DF 2048
#define NE 8
#define MCAP 8192

// ---------------- scratch (device globals; no runtime allocation) ----------
__device__ int   g_count[NE];
__device__ int   g_slot_token[NE * MCAP];          // per-expert compacted token ids
__device__ int   g_token_slot[T_TOKENS * 2];       // per-token: global slot row (e*MCAP+s)
__device__ float g_token_w[T_TOKENS * 2];          // per-token: renormalized top-2 weights
__device__ float g_h_routed[(size_t)NE * MCAP * DF];    // 512 MB
__device__ float g_eo_routed[(size_t)NE * MCAP * DM];   // 256 MB
__device__ float g_h_shared[(size_t)T_TOKENS * DF];     // 64 MB

// ---------------- tiny utility kernels -------------------------------------
__global__ void zero_counts_kernel() {
    if (threadIdx.x < NE) g_count[threadIdx.x] = 0;
}

// ---------------- gating: 1 warp per token ---------------------------------
__global__ void gate_kernel(const float* __restrict__ x,
                            const float* __restrict__ gw) {
    int gtid = blockIdx.x * blockDim.x + threadIdx.x;
    int t = gtid >> 5;
    int lane = threadIdx.x & 31;
    if (t >= T_TOKENS) return;

    const float* xr = x + (size_t)t * DM;
    float acc[NE];
#pragma unroll
    for (int e = 0; e < NE; e++) acc[e] = 0.f;

    for (int d = lane; d < DM; d += 32) {
        float xv = xr[d];
#pragma unroll
        for (int e = 0; e < NE; e++) acc[e] += xv * gw[e * DM + d];
    }
#pragma unroll
    for (int e = 0; e < NE; e++) {
#pragma unroll
        for (int o = 16; o > 0; o >>= 1)
            acc[e] += __shfl_xor_sync(0xffffffffu, acc[e], o);
    }

    if (lane == 0) {
        float m = acc[0];
#pragma unroll
        for (int e = 1; e < NE; e++) m = fmaxf(m, acc[e]);
        float p[NE], s = 0.f;
#pragma unroll
        for (int e = 0; e < NE; e++) { p[e] = expf(acc[e] - m); s += p[e]; }
        float inv_s = 1.f / s;
#pragma unroll
        for (int e = 0; e < NE; e++) p[e] *= inv_s;

        // top-2 (first index wins ties, matching jax.lax.top_k)
        int i0 = 0;
#pragma unroll
        for (int e = 1; e < NE; e++) if (p[e] > p[i0]) i0 = e;
        int i1 = (i0 == 0) ? 1 : 0;
#pragma unroll
        for (int e = 0; e < NE; e++)
            if (e != i0 && p[e] > p[i1]) i1 = e;

        float w0 = p[i0], w1 = p[i1];
        float inv = 1.f / (w0 + w1 + 1e-20f);
        w0 *= inv; w1 *= inv;

        int s0 = atomicAdd(&g_count[i0], 1);
        g_slot_token[i0 * MCAP + s0] = t;
        g_token_slot[t * 2 + 0] = i0 * MCAP + s0;
        g_token_w[t * 2 + 0] = w0;

        int s1 = atomicAdd(&g_count[i1], 1);
        g_slot_token[i1 * MCAP + s1] = t;
        g_token_slot[t * 2 + 1] = i1 * MCAP + s1;
        g_token_w[t * 2 + 1] = w1;
    }
}

// ---------------- fp32 NT GEMM: C[m,n] = relu?(sum_k A[m,k]*B[n,k] + bias[n])
// 128x128x8 block tile, 256 threads, 8x8 microtile.
// blockIdx.z = expert. Row count can come from device (counts) or be fixed.
// Optional row gather for A (routed GEMM1 reads x via token ids).
__global__ void __launch_bounds__(256, 2)
gemm_nt_kernel(const float* __restrict__ A,
               const float* __restrict__ Bw,
               const float* __restrict__ bias,
               float* __restrict__ C,
               const int* __restrict__ counts,
               const int* __restrict__ gather,
               int Mfixed, int N, int K, int lda,
               long long aExpStride, long long cExpStride,
               int relu) {
    const int e = blockIdx.z;
    const int M = counts ? counts[e] : Mfixed;
    const int row0 = blockIdx.x * 128;
    if (row0 >= M) return;
    const int col0 = blockIdx.y * 128;

    const float* Ae = A + (long long)e * aExpStride;
    const float* Be = Bw + (long long)e * (long long)N * K;
    const float* be = bias + (long long)e * N;
    float* Ce = C + (long long)e * cExpStride;
    const int* ge = gather ? gather + e * MCAP : (const int*)0;

    __shared__ float As[8][132];
    __shared__ float Bs[8][132];

    const int tid = threadIdx.x;
    const int ar = tid >> 1;              // 0..127
    const int ac = (tid & 1) * 4;         // 0 or 4

    const int arow = row0 + ar;
    const bool avalid = arow < M;
    long long asrc = 0;
    if (avalid) asrc = ge ? (long long)ge[arow] : (long long)arow;
    const float* aptr = Ae + asrc * lda + ac;
    const float* bptr = Be + (long long)(col0 + ar) * K + ac;

    const int tx = tid & 15;              // col group: cols tx*8..tx*8+7
    const int ty = tid >> 4;              // row group: rows ty*8..ty*8+7

    float acc[8][8];
#pragma unroll
    for (int i = 0; i < 8; i++)
#pragma unroll
        for (int j = 0; j < 8; j++) acc[i][j] = 0.f;

    float4 av = avalid ? *(const float4*)(aptr) : make_float4(0.f, 0.f, 0.f, 0.f);
    float4 bv = *(const float4*)(bptr);

    int k0 = 0;
    while (true) {
        As[ac + 0][ar] = av.x; As[ac + 1][ar] = av.y;
        As[ac + 2][ar] = av.z; As[ac + 3][ar] = av.w;
        Bs[ac + 0][ar] = bv.x; Bs[ac + 1][ar] = bv.y;
        Bs[ac + 2][ar] = bv.z; Bs[ac + 3][ar] = bv.w;
        __syncthreads();

        k0 += 8;
        const bool more = k0 < K;
        float4 av2, bv2;
        if (more) {
            av2 = avalid ? *(const float4*)(aptr + k0) : make_float4(0.f, 0.f, 0.f, 0.f);
            bv2 = *(const float4*)(bptr + k0);
        }

#pragma unroll
        for (int kk = 0; kk < 8; kk++) {
            float4 a0 = *(const float4*)&As[kk][ty * 8];
            float4 a1 = *(const float4*)&As[kk][ty * 8 + 4];
            float4 b0 = *(const float4*)&Bs[kk][tx * 8];
            float4 b1 = *(const float4*)&Bs[kk][tx * 8 + 4];
            float a[8] = {a0.x, a0.y, a0.z, a0.w, a1.x, a1.y, a1.z, a1.w};
            float b[8] = {b0.x, b0.y, b0.z, b0.w, b1.x, b1.y, b1.z, b1.w};
#pragma unroll
            for (int i = 0; i < 8; i++)
#pragma unroll
                for (int j = 0; j < 8; j++) acc[i][j] = fmaf(a[i], b[j], acc[i][j]);
        }
        __syncthreads();
        if (!more) break;
        av = av2; bv = bv2;
    }

    // epilogue
    float bvals[8];
#pragma unroll
    for (int j = 0; j < 8; j++) bvals[j] = be[col0 + tx * 8 + j];

#pragma unroll
    for (int i = 0; i < 8; i++) {
        int r = row0 + ty * 8 + i;
        if (r < M) {
            float v[8];
#pragma unroll
            for (int j = 0; j < 8; j++) {
                v[j] = acc[i][j] + bvals[j];
                if (relu) v[j] = fmaxf(v[j], 0.f);
            }
            float* crow = Ce + (long long)r * N + col0 + tx * 8;
            *(float4*)(crow) = make_float4(v[0], v[1], v[2], v[3]);
            *(float4*)(crow + 4) = make_float4(v[4], v[5], v[6], v[7]);
        }
    }
}

// ---------------- combine: out[t] += w0*eo[slot0] + w1*eo[slot1] ------------
__global__ void combine_kernel(float* __restrict__ out) {
    int t = blockIdx.x;
    int s0 = g_token_slot[t * 2 + 0];
    int s1 = g_token_slot[t * 2 + 1];
    float w0 = g_token_w[t * 2 + 0];
    float w1 = g_token_w[t * 2 + 1];
    const float* e0 = g_eo_routed + (size_t)s0 * DM;
    const float* e1 = g_eo_routed + (size_t)s1 * DM;
    float* o = out + (size_t)t * DM;
    for (int d = threadIdx.x; d < DM; d += blockDim.x)
        o[d] += w0 * e0[d] + w1 * e1[d];
}

// ---------------- host launch ----------------------------------------------
extern "C" void kernel_launch(void* const* d_in, const int* in_sizes, int n_in,
                              void* d_out, int out_size) {
    const float* x      = (const float*)d_in[0];
    const float* gate_w = (const float*)d_in[1];
    const float* w1     = (const float*)d_in[2];
    const float* b1     = (const float*)d_in[3];
    const float* w2     = (const float*)d_in[4];
    const float* b2     = (const float*)d_in[5];
    const float* ws1    = (const float*)d_in[6];
    const float* bs1    = (const float*)d_in[7];
    const float* ws2    = (const float*)d_in[8];
    const float* bs2    = (const float*)d_in[9];
    float* out = (float*)d_out;

    int* count_p;  int* slot_p;
    float* hr_p;   float* eor_p; float* hs_p;
    cudaGetSymbolAddress((void**)&count_p, g_count);
    cudaGetSymbolAddress((void**)&slot_p,  g_slot_token);
    cudaGetSymbolAddress((void**)&hr_p,    g_h_routed);
    cudaGetSymbolAddress((void**)&eor_p,   g_eo_routed);
    cudaGetSymbolAddress((void**)&hs_p,    g_h_shared);

    // 1) reset routing counters
    zero_counts_kernel<<<1, 32>>>();

    // 2) gate + route (1 warp / token)
    gate_kernel<<<(T_TOKENS * 32) / 256, 256>>>(x, gate_w);

    // 3) routed GEMM1: h[e,s,:] = relu(x[tok(e,s)] @ w1[e]^T + b1[e])
    {
        dim3 grid(MCAP / 128, DF / 128, NE);
        gemm_nt_kernel<<<grid, 256>>>(x, w1, b1, hr_p,
                                      count_p, slot_p,
                                      0, DF, DM, DM,
                                      0LL, (long long)MCAP * DF, 1);
    }
    // 4) routed GEMM2: eo[e,s,:] = h[e,s,:] @ w2[e]^T + b2[e]
    {
        dim3 grid(MCAP / 128, DM / 128, NE);
        gemm_nt_kernel<<<grid, 256>>>(hr_p, w2, b2, eor_p,
                                      count_p, (const int*)0,
                                      0, DM, DF, DF,
                                      (long long)MCAP * DF, (long long)MCAP * DM, 0);
    }
    // 5) shared GEMM1: h_s = relu(x @ ws1^T + bs1)
    {
        dim3 grid(T_TOKENS / 128, DF / 128, 1);
        gemm_nt_kernel<<<grid, 256>>>(x, ws1, bs1, hs_p,
                                      (const int*)0, (const int*)0,
                                      T_TOKENS, DF, DM, DM,
                                      0LL, 0LL, 1);
    }
    // 6) shared GEMM2: out = h_s @ ws2^T + bs2   (initializes out)
    {
        dim3 grid(T_TOKENS / 128, DM / 128, 1);
        gemm_nt_kernel<<<grid, 256>>>(hs_p, ws2, bs2, out,
                                      (const int*)0, (const int*)0,
                                      T_TOKENS, DM, DF, DF,
                                      0LL, 0LL, 0);
    }
    // 7) combine routed contributions into out
    combine_kernel<<<T_TOKENS, 256>>>(out);
}

// round 6
// speedup vs baseline: 2.4061x; 2.4061x over previous
#include <cuda_runtime.h>
#include <cuda_bf16.h>
#include <stdint.h>
#include <math.h>

#define T_TOKENS 8192
#define DM 1024
#define DF 2048
#define NE 8
#define MCAP 8192

// ===================== scratch (device globals) =============================
__device__ int   g_count[NE];
__device__ int   g_slot_token[NE * MCAP];
__device__ int   g_token_slot[T_TOKENS * 2];
__device__ float g_token_w[T_TOKENS * 2];

__device__ __nv_bfloat16 g_xh [(size_t)T_TOKENS * DM];
__device__ __nv_bfloat16 g_xl [(size_t)T_TOKENS * DM];
__device__ __nv_bfloat16 g_w1h[(size_t)NE * DF * DM];
__device__ __nv_bfloat16 g_w1l[(size_t)NE * DF * DM];
__device__ __nv_bfloat16 g_w2h[(size_t)NE * DM * DF];
__device__ __nv_bfloat16 g_w2l[(size_t)NE * DM * DF];
__device__ __nv_bfloat16 g_ws1h[(size_t)DF * DM];
__device__ __nv_bfloat16 g_ws1l[(size_t)DF * DM];
__device__ __nv_bfloat16 g_ws2h[(size_t)DM * DF];
__device__ __nv_bfloat16 g_ws2l[(size_t)DM * DF];
__device__ __nv_bfloat16 g_hh [(size_t)NE * MCAP * DF];
__device__ __nv_bfloat16 g_hl [(size_t)NE * MCAP * DF];
__device__ __nv_bfloat16 g_hsh[(size_t)T_TOKENS * DF];
__device__ __nv_bfloat16 g_hsl[(size_t)T_TOKENS * DF];
__device__ float g_eo[(size_t)NE * MCAP * DM];

// ===================== PTX helpers (plain sm_80+ features only) =============
__device__ __forceinline__ uint32_t smem_u32(const void* p) {
    uint32_t a;
    asm("{ .reg .u64 t; cvta.to.shared.u64 t, %1; cvt.u32.u64 %0, t; }"
        : "=r"(a) : "l"(p));
    return a;
}
__device__ __forceinline__ void ldsm4(uint32_t* r, uint32_t addr) {
    asm volatile("ldmatrix.sync.aligned.m8n8.x4.shared.b16 {%0,%1,%2,%3}, [%4];"
                 : "=r"(r[0]), "=r"(r[1]), "=r"(r[2]), "=r"(r[3]) : "r"(addr));
}
__device__ __forceinline__ void mma_bf16(float* c, const uint32_t* a,
                                         const uint32_t* b) {
    asm volatile(
        "mma.sync.aligned.m16n8k16.row.col.f32.bf16.bf16.f32 "
        "{%0,%1,%2,%3}, {%4,%5,%6,%7}, {%8,%9}, {%0,%1,%2,%3};"
        : "+f"(c[0]), "+f"(c[1]), "+f"(c[2]), "+f"(c[3])
        : "r"(a[0]), "r"(a[1]), "r"(a[2]), "r"(a[3]), "r"(b[0]), "r"(b[1]));
}
#define CPA(sm, gp) \
    asm volatile("cp.async.cg.shared.global [%0], [%1], 16;" :: "r"(sm), "l"(gp))
#define CP_COMMIT() asm volatile("cp.async.commit_group;" ::: "memory")
#define CP_WAIT1()  asm volatile("cp.async.wait_group 1;" ::: "memory")
#define CP_WAIT0()  asm volatile("cp.async.wait_group 0;" ::: "memory")

// ===================== small kernels ========================================
__global__ void zero_counts_kernel() {
    if (threadIdx.x < NE) g_count[threadIdx.x] = 0;
}

__global__ void gate_kernel(const float* __restrict__ x,
                            const float* __restrict__ gw) {
    int gtid = blockIdx.x * blockDim.x + threadIdx.x;
    int t = gtid >> 5;
    int lane = threadIdx.x & 31;
    if (t >= T_TOKENS) return;

    const float* xr = x + (size_t)t * DM;
    float acc[NE];
#pragma unroll
    for (int e = 0; e < NE; e++) acc[e] = 0.f;
    for (int d = lane; d < DM; d += 32) {
        float xv = xr[d];
#pragma unroll
        for (int e = 0; e < NE; e++) acc[e] += xv * gw[e * DM + d];
    }
#pragma unroll
    for (int e = 0; e < NE; e++)
#pragma unroll
        for (int o = 16; o > 0; o >>= 1)
            acc[e] += __shfl_xor_sync(0xffffffffu, acc[e], o);

    if (lane == 0) {
        float m = acc[0];
#pragma unroll
        for (int e = 1; e < NE; e++) m = fmaxf(m, acc[e]);
        float p[NE], s = 0.f;
#pragma unroll
        for (int e = 0; e < NE; e++) { p[e] = expf(acc[e] - m); s += p[e]; }
        float inv_s = 1.f / s;
#pragma unroll
        for (int e = 0; e < NE; e++) p[e] *= inv_s;
        int i0 = 0;
#pragma unroll
        for (int e = 1; e < NE; e++) if (p[e] > p[i0]) i0 = e;
        int i1 = (i0 == 0) ? 1 : 0;
#pragma unroll
        for (int e = 0; e < NE; e++)
            if (e != i0 && p[e] > p[i1]) i1 = e;
        float w0 = p[i0], w1 = p[i1];
        float inv = 1.f / (w0 + w1 + 1e-20f);
        w0 *= inv; w1 *= inv;
        int s0 = atomicAdd(&g_count[i0], 1);
        g_slot_token[i0 * MCAP + s0] = t;
        g_token_slot[t * 2 + 0] = i0 * MCAP + s0;
        g_token_w[t * 2 + 0] = w0;
        int s1 = atomicAdd(&g_count[i1], 1);
        g_slot_token[i1 * MCAP + s1] = t;
        g_token_slot[t * 2 + 1] = i1 * MCAP + s1;
        g_token_w[t * 2 + 1] = w1;
    }
}

// fp32 -> (bf16 hi, bf16 lo), vectorized by 4
__global__ void split_kernel(const float* __restrict__ src,
                             __nv_bfloat16* __restrict__ hi,
                             __nv_bfloat16* __restrict__ lo, int n4) {
    int i = blockIdx.x * blockDim.x + threadIdx.x;
    if (i >= n4) return;
    float4 v = ((const float4*)src)[i];
    __nv_bfloat16 h0 = __float2bfloat16(v.x);
    __nv_bfloat16 h1 = __float2bfloat16(v.y);
    __nv_bfloat16 h2 = __float2bfloat16(v.z);
    __nv_bfloat16 h3 = __float2bfloat16(v.w);
    __nv_bfloat16 l0 = __float2bfloat16(v.x - __bfloat162float(h0));
    __nv_bfloat16 l1 = __float2bfloat16(v.y - __bfloat162float(h1));
    __nv_bfloat16 l2 = __float2bfloat16(v.z - __bfloat162float(h2));
    __nv_bfloat16 l3 = __float2bfloat16(v.w - __bfloat162float(h3));
    uint32_t hp0 = ((uint32_t)__bfloat16_as_ushort(h1) << 16) | __bfloat16_as_ushort(h0);
    uint32_t hp1 = ((uint32_t)__bfloat16_as_ushort(h3) << 16) | __bfloat16_as_ushort(h2);
    uint32_t lp0 = ((uint32_t)__bfloat16_as_ushort(l1) << 16) | __bfloat16_as_ushort(l0);
    uint32_t lp1 = ((uint32_t)__bfloat16_as_ushort(l3) << 16) | __bfloat16_as_ushort(l2);
    ((uint2*)hi)[i] = make_uint2(hp0, hp1);
    ((uint2*)lo)[i] = make_uint2(lp0, lp1);
}

__global__ void combine_kernel(float* __restrict__ out) {
    int t = blockIdx.x;
    int tid = threadIdx.x;
    int s0 = g_token_slot[t * 2 + 0];
    int s1 = g_token_slot[t * 2 + 1];
    float w0 = g_token_w[t * 2 + 0];
    float w1 = g_token_w[t * 2 + 1];
    const float4* e0 = (const float4*)(g_eo + (size_t)s0 * DM);
    const float4* e1 = (const float4*)(g_eo + (size_t)s1 * DM);
    float4* o = (float4*)(out + (size_t)t * DM);
    float4 a = e0[tid], b = e1[tid], c = o[tid];
    c.x += w0 * a.x + w1 * b.x;
    c.y += w0 * a.y + w1 * b.y;
    c.z += w0 * a.z + w1 * b.z;
    c.w += w0 * a.w + w1 * b.w;
    o[tid] = c;
}

// ===================== mma.sync GEMM ========================================
// C[M,N] = A[M,K] @ B[N,K]^T + bias, fp32-accurate via bf16 hi/lo 3-MMA split.
// 128x128x32 block tile, 256 threads = 8 warps (2x4), warp tile 64x32.
// cp.async double-buffered smem; padded rows (80B) -> conflict-free ldmatrix.
#define BM 128
#define BN 128
#define BK 32
#define ROWB 80                         // bytes per smem row (64 used + 16 pad)
#define ARRB (128 * ROWB)               // 10240 bytes per array
#define STAGEB (4 * ARRB)               // Ah, Al, Bh, Bl
#define SMEM_TOTAL_GEMM (2 * STAGEB)    // 81920

__global__ void __launch_bounds__(256)
mma_gemm(const __nv_bfloat16* __restrict__ Ah,
         const __nv_bfloat16* __restrict__ Al,
         const __nv_bfloat16* __restrict__ Bh,
         const __nv_bfloat16* __restrict__ Bl,
         const float* __restrict__ bias,
         float* __restrict__ Cf,
         __nv_bfloat16* __restrict__ Chi,
         __nv_bfloat16* __restrict__ Clo,
         const int* __restrict__ counts,
         const int* __restrict__ gather,
         int Mfixed, int N, int K,
         long long aStride,    // rows per expert in A (0 with gather)
         long long cStride,    // rows per expert in C
         int mode)             // 0: fp32 out; 1: relu + bf16 hi/lo out
{
    const int e = blockIdx.z;
    const int M = counts ? counts[e] : Mfixed;
    const int row0 = blockIdx.x * BM;
    if (row0 >= M) return;
    const int col0 = blockIdx.y * BN;

    extern __shared__ char smem[];
    const uint32_t sb = smem_u32(smem);
    const int tid = threadIdx.x;
    const int wid = tid >> 5;
    const int lane = tid & 31;

    // ---- cp.async setup: 8 x 16B per thread per chunk ----------------------
    const int lrow = tid >> 2;          // 0..63
    const int seg = tid & 3;            // 16B segment within 64B row
    int ra0 = row0 + lrow, ra1 = row0 + 64 + lrow;
    int ca0 = (ra0 < M) ? ra0 : (M - 1);
    int ca1 = (ra1 < M) ? ra1 : (M - 1);
    long long ga0 = (long long)e * aStride +
                    (gather ? (long long)gather[(size_t)e * MCAP + ca0] : (long long)ca0);
    long long ga1 = (long long)e * aStride +
                    (gather ? (long long)gather[(size_t)e * MCAP + ca1] : (long long)ca1);
    long long gb0 = (long long)e * N + col0 + lrow;
    long long gb1 = gb0 + 64;

    const char* pAh0 = (const char*)(Ah + (size_t)ga0 * K) + seg * 16;
    const char* pAh1 = (const char*)(Ah + (size_t)ga1 * K) + seg * 16;
    const char* pAl0 = (const char*)(Al + (size_t)ga0 * K) + seg * 16;
    const char* pAl1 = (const char*)(Al + (size_t)ga1 * K) + seg * 16;
    const char* pBh0 = (const char*)(Bh + (size_t)gb0 * K) + seg * 16;
    const char* pBh1 = (const char*)(Bh + (size_t)gb1 * K) + seg * 16;
    const char* pBl0 = (const char*)(Bl + (size_t)gb0 * K) + seg * 16;
    const char* pBl1 = (const char*)(Bl + (size_t)gb1 * K) + seg * 16;

    const uint32_t so0 = lrow * ROWB + seg * 16;
    const uint32_t so1 = (64 + lrow) * ROWB + seg * 16;

#define ISSUE(cc, st) do {                                                     \
    uint32_t _s = sb + (st) * STAGEB;                                          \
    size_t _g = (size_t)(cc) * 64;                                             \
    CPA(_s + so0,            pAh0 + _g);                                       \
    CPA(_s + so1,            pAh1 + _g);                                       \
    CPA(_s + ARRB + so0,     pAl0 + _g);                                       \
    CPA(_s + ARRB + so1,     pAl1 + _g);                                       \
    CPA(_s + 2 * ARRB + so0, pBh0 + _g);                                       \
    CPA(_s + 2 * ARRB + so1, pBh1 + _g);                                       \
    CPA(_s + 3 * ARRB + so0, pBl0 + _g);                                       \
    CPA(_s + 3 * ARRB + so1, pBl1 + _g);                                       \
    CP_COMMIT();                                                               \
} while (0)

    // ---- fragment addressing ----------------------------------------------
    const int warp_m = wid >> 2;        // 0..1
    const int warp_n = wid & 3;         // 0..3
    const int arow = (lane & 7) + ((lane >> 3) & 1) * 8;
    const int akk = ((lane >> 4) & 1) * 8;
    const int brow = (lane & 7) + ((lane >> 4) & 1) * 8;
    const int bkk = ((lane >> 3) & 1) * 8;

    float acc[4][4][4];
#pragma unroll
    for (int mi = 0; mi < 4; mi++)
#pragma unroll
        for (int ni = 0; ni < 4; ni++)
#pragma unroll
            for (int q = 0; q < 4; q++) acc[mi][ni][q] = 0.f;

    ISSUE(0, 0);
    const int NC = K / BK;

    for (int c = 0; c < NC; c++) {
        const int st = c & 1;
        if (c + 1 < NC) { ISSUE(c + 1, st ^ 1); CP_WAIT1(); }
        else            { CP_WAIT0(); }
        __syncthreads();

        const uint32_t sbase = sb + st * STAGEB;
#pragma unroll
        for (int ks = 0; ks < 2; ks++) {
            uint32_t ahi[4][4], alo[4][4], bhi[4][2], blo[4][2];
#pragma unroll
            for (int mi = 0; mi < 4; mi++) {
                uint32_t ad = sbase +
                    (warp_m * 64 + mi * 16 + arow) * ROWB + (ks * 16 + akk) * 2;
                ldsm4(ahi[mi], ad);
                ldsm4(alo[mi], ad + ARRB);
            }
#pragma unroll
            for (int np = 0; np < 2; np++) {
                uint32_t bd = sbase + 2 * ARRB +
                    (warp_n * 32 + np * 16 + brow) * ROWB + (ks * 16 + bkk) * 2;
                uint32_t t0[4], t1[4];
                ldsm4(t0, bd);
                ldsm4(t1, bd + ARRB);
                bhi[np * 2][0] = t0[0]; bhi[np * 2][1] = t0[1];
                bhi[np * 2 + 1][0] = t0[2]; bhi[np * 2 + 1][1] = t0[3];
                blo[np * 2][0] = t1[0]; blo[np * 2][1] = t1[1];
                blo[np * 2 + 1][0] = t1[2]; blo[np * 2 + 1][1] = t1[3];
            }
#pragma unroll
            for (int mi = 0; mi < 4; mi++)
#pragma unroll
                for (int ni = 0; ni < 4; ni++) {
                    mma_bf16(acc[mi][ni], ahi[mi], bhi[ni]);
                    mma_bf16(acc[mi][ni], ahi[mi], blo[ni]);
                    mma_bf16(acc[mi][ni], alo[mi], bhi[ni]);
                }
        }
        __syncthreads();
    }

    // ---- epilogue ----------------------------------------------------------
    const float* biasp = bias + (counts ? (size_t)e * N : 0);
    const int rin = lane >> 2;
    const int cpair = (lane & 3) * 2;

#pragma unroll
    for (int mi = 0; mi < 4; mi++) {
#pragma unroll
        for (int half = 0; half < 2; half++) {
            int rr = row0 + warp_m * 64 + mi * 16 + half * 8 + rin;
            if (rr >= M) continue;
            size_t crow = (size_t)e * cStride + rr;
#pragma unroll
            for (int ni = 0; ni < 4; ni++) {
                int col = col0 + warp_n * 32 + ni * 8 + cpair;
                float2 bv = *(const float2*)(biasp + col);
                float v0 = acc[mi][ni][half * 2 + 0] + bv.x;
                float v1 = acc[mi][ni][half * 2 + 1] + bv.y;
                if (mode) {
                    v0 = fmaxf(v0, 0.f);
                    v1 = fmaxf(v1, 0.f);
                    __nv_bfloat16 h0 = __float2bfloat16(v0);
                    __nv_bfloat16 h1 = __float2bfloat16(v1);
                    __nv_bfloat16 l0 = __float2bfloat16(v0 - __bfloat162float(h0));
                    __nv_bfloat16 l1 = __float2bfloat16(v1 - __bfloat162float(h1));
                    uint32_t hp = ((uint32_t)__bfloat16_as_ushort(h1) << 16) |
                                  __bfloat16_as_ushort(h0);
                    uint32_t lp = ((uint32_t)__bfloat16_as_ushort(l1) << 16) |
                                  __bfloat16_as_ushort(l0);
                    *(uint32_t*)(Chi + crow * N + col) = hp;
                    *(uint32_t*)(Clo + crow * N + col) = lp;
                } else {
                    *(float2*)(Cf + crow * N + col) = make_float2(v0, v1);
                }
            }
        }
    }
#undef ISSUE
}

// ===================== host launch ==========================================
extern "C" void kernel_launch(void* const* d_in, const int* in_sizes, int n_in,
                              void* d_out, int out_size) {
    const float* x      = (const float*)d_in[0];
    const float* gate_w = (const float*)d_in[1];
    const float* w1     = (const float*)d_in[2];
    const float* b1     = (const float*)d_in[3];
    const float* w2     = (const float*)d_in[4];
    const float* b2     = (const float*)d_in[5];
    const float* ws1    = (const float*)d_in[6];
    const float* bs1    = (const float*)d_in[7];
    const float* ws2    = (const float*)d_in[8];
    const float* bs2    = (const float*)d_in[9];
    float* out = (float*)d_out;

    int *count_p, *slot_p;
    __nv_bfloat16 *xh, *xl, *w1h, *w1l, *w2h, *w2l, *ws1h, *ws1l, *ws2h, *ws2l;
    __nv_bfloat16 *hh, *hl, *hsh, *hsl;
    float* eo;
    cudaGetSymbolAddress((void**)&count_p, g_count);
    cudaGetSymbolAddress((void**)&slot_p,  g_slot_token);
    cudaGetSymbolAddress((void**)&xh,  g_xh);   cudaGetSymbolAddress((void**)&xl,  g_xl);
    cudaGetSymbolAddress((void**)&w1h, g_w1h);  cudaGetSymbolAddress((void**)&w1l, g_w1l);
    cudaGetSymbolAddress((void**)&w2h, g_w2h);  cudaGetSymbolAddress((void**)&w2l, g_w2l);
    cudaGetSymbolAddress((void**)&ws1h, g_ws1h); cudaGetSymbolAddress((void**)&ws1l, g_ws1l);
    cudaGetSymbolAddress((void**)&ws2h, g_ws2h); cudaGetSymbolAddress((void**)&ws2l, g_ws2l);
    cudaGetSymbolAddress((void**)&hh,  g_hh);   cudaGetSymbolAddress((void**)&hl,  g_hl);
    cudaGetSymbolAddress((void**)&hsh, g_hsh);  cudaGetSymbolAddress((void**)&hsl, g_hsl);
    cudaGetSymbolAddress((void**)&eo,  g_eo);

    cudaFuncSetAttribute(mma_gemm, cudaFuncAttributeMaxDynamicSharedMemorySize,
                         SMEM_TOTAL_GEMM);

    // 1) routing
    zero_counts_kernel<<<1, 32>>>();
    gate_kernel<<<(T_TOKENS * 32) / 256, 256>>>(x, gate_w);

    // 2) fp32 -> bf16 hi/lo splits
    {
        int n;
        n = T_TOKENS * DM;      split_kernel<<<n / 4 / 256, 256>>>(x,   xh,  xl,  n / 4);
        n = NE * DF * DM;       split_kernel<<<n / 4 / 256, 256>>>(w1,  w1h, w1l, n / 4);
        n = NE * DM * DF;       split_kernel<<<n / 4 / 256, 256>>>(w2,  w2h, w2l, n / 4);
        n = DF * DM;            split_kernel<<<n / 4 / 256, 256>>>(ws1, ws1h, ws1l, n / 4);
        n = DM * DF;            split_kernel<<<n / 4 / 256, 256>>>(ws2, ws2h, ws2l, n / 4);
    }

    // 3) routed GEMM1: h = relu(x[gather] @ w1^T + b1) -> bf16 hi/lo
    {
        dim3 grid(MCAP / BM, DF / BN, NE);
        mma_gemm<<<grid, 256, SMEM_TOTAL_GEMM>>>(
            xh, xl, w1h, w1l, b1, (float*)0, hh, hl,
            count_p, slot_p, 0, DF, DM, 0LL, (long long)MCAP, 1);
    }
    // 4) routed GEMM2: eo = h @ w2^T + b2 -> fp32
    {
        dim3 grid(MCAP / BM, DM / BN, NE);
        mma_gemm<<<grid, 256, SMEM_TOTAL_GEMM>>>(
            hh, hl, w2h, w2l, b2, eo, (__nv_bfloat16*)0, (__nv_bfloat16*)0,
            count_p, (const int*)0, 0, DM, DF,
            (long long)MCAP, (long long)MCAP, 0);
    }
    // 5) shared GEMM1: hs = relu(x @ ws1^T + bs1) -> bf16 hi/lo
    {
        dim3 grid(T_TOKENS / BM, DF / BN, 1);
        mma_gemm<<<grid, 256, SMEM_TOTAL_GEMM>>>(
            xh, xl, ws1h, ws1l, bs1, (float*)0, hsh, hsl,
            (const int*)0, (const int*)0, T_TOKENS, DF, DM, 0LL, 0LL, 1);
    }
    // 6) shared GEMM2: out = hs @ ws2^T + bs2 -> fp32 (initializes out)
    {
        dim3 grid(T_TOKENS / BM, DM / BN, 1);
        mma_gemm<<<grid, 256, SMEM_TOTAL_GEMM>>>(
            hsh, hsl, ws2h, ws2l, bs2, out, (__nv_bfloat16*)0, (__nv_bfloat16*)0,
            (const int*)0, (const int*)0, T_TOKENS, DM, DF, 0LL, 0LL, 0);
    }
    // 7) combine routed into out
    combine_kernel<<<T_TOKENS, 256>>>(out);
}

// round 9
// speedup vs baseline: 2.5852x; 1.0744x over previous
#include <cuda_runtime.h>
#include <cuda_bf16.h>
#include <stdint.h>
#include <math.h>

#define T_TOKENS 8192
#define DM 1024
#define DF 2048
#define NE 8
#define MCAP 8192

// ===================== scratch (device globals) =============================
__device__ int   g_count[NE];
__device__ int   g_slot_token[NE * MCAP];
__device__ int   g_token_slot[T_TOKENS * 2];
__device__ float g_token_w[T_TOKENS * 2];

__device__ __nv_bfloat16 g_xh [(size_t)T_TOKENS * DM];
__device__ __nv_bfloat16 g_xl [(size_t)T_TOKENS * DM];
__device__ __nv_bfloat16 g_w1h[(size_t)NE * DF * DM];
__device__ __nv_bfloat16 g_w1l[(size_t)NE * DF * DM];
__device__ __nv_bfloat16 g_w2h[(size_t)NE * DM * DF];
__device__ __nv_bfloat16 g_w2l[(size_t)NE * DM * DF];
__device__ __nv_bfloat16 g_ws1h[(size_t)DF * DM];
__device__ __nv_bfloat16 g_ws1l[(size_t)DF * DM];
__device__ __nv_bfloat16 g_ws2h[(size_t)DM * DF];
__device__ __nv_bfloat16 g_ws2l[(size_t)DM * DF];
__device__ __nv_bfloat16 g_hh [(size_t)NE * MCAP * DF];
__device__ __nv_bfloat16 g_hl [(size_t)NE * MCAP * DF];
__device__ __nv_bfloat16 g_hsh[(size_t)T_TOKENS * DF];
__device__ __nv_bfloat16 g_hsl[(size_t)T_TOKENS * DF];
__device__ float g_eo[(size_t)NE * MCAP * DM];

// ===================== PTX helpers (plain sm_80+ features only) =============
__device__ __forceinline__ uint32_t smem_u32(const void* p) {
    uint32_t a;
    asm("{ .reg .u64 t; cvta.to.shared.u64 t, %1; cvt.u32.u64 %0, t; }"
        : "=r"(a) : "l"(p));
    return a;
}
__device__ __forceinline__ void ldsm4(uint32_t* r, uint32_t addr) {
    asm volatile("ldmatrix.sync.aligned.m8n8.x4.shared.b16 {%0,%1,%2,%3}, [%4];"
                 : "=r"(r[0]), "=r"(r[1]), "=r"(r[2]), "=r"(r[3]) : "r"(addr));
}
__device__ __forceinline__ void mma_bf16(float* c, const uint32_t* a,
                                         const uint32_t* b) {
    asm volatile(
        "mma.sync.aligned.m16n8k16.row.col.f32.bf16.bf16.f32 "
        "{%0,%1,%2,%3}, {%4,%5,%6,%7}, {%8,%9}, {%0,%1,%2,%3};"
        : "+f"(c[0]), "+f"(c[1]), "+f"(c[2]), "+f"(c[3])
        : "r"(a[0]), "r"(a[1]), "r"(a[2]), "r"(a[3]), "r"(b[0]), "r"(b[1]));
}
#define CPA(sm, gp) \
    asm volatile("cp.async.cg.shared.global [%0], [%1], 16;" :: "r"(sm), "l"(gp))
#define CP_COMMIT() asm volatile("cp.async.commit_group;" ::: "memory")
#define CP_WAIT1()  asm volatile("cp.async.wait_group 1;" ::: "memory")

// ===================== small kernels ========================================
__global__ void zero_counts_kernel() {
    if (threadIdx.x < NE) g_count[threadIdx.x] = 0;
}

__global__ void gate_kernel(const float* __restrict__ x,
                            const float* __restrict__ gw) {
    int gtid = blockIdx.x * blockDim.x + threadIdx.x;
    int t = gtid >> 5;
    int lane = threadIdx.x & 31;
    if (t >= T_TOKENS) return;

    const float* xr = x + (size_t)t * DM;
    float acc[NE];
#pragma unroll
    for (int e = 0; e < NE; e++) acc[e] = 0.f;
    for (int d = lane; d < DM; d += 32) {
        float xv = xr[d];
#pragma unroll
        for (int e = 0; e < NE; e++) acc[e] += xv * gw[e * DM + d];
    }
#pragma unroll
    for (int e = 0; e < NE; e++)
#pragma unroll
        for (int o = 16; o > 0; o >>= 1)
            acc[e] += __shfl_xor_sync(0xffffffffu, acc[e], o);

    if (lane == 0) {
        float m = acc[0];
#pragma unroll
        for (int e = 1; e < NE; e++) m = fmaxf(m, acc[e]);
        float p[NE], s = 0.f;
#pragma unroll
        for (int e = 0; e < NE; e++) { p[e] = expf(acc[e] - m); s += p[e]; }
        float inv_s = 1.f / s;
#pragma unroll
        for (int e = 0; e < NE; e++) p[e] *= inv_s;
        int i0 = 0;
#pragma unroll
        for (int e = 1; e < NE; e++) if (p[e] > p[i0]) i0 = e;
        int i1 = (i0 == 0) ? 1 : 0;
#pragma unroll
        for (int e = 0; e < NE; e++)
            if (e != i0 && p[e] > p[i1]) i1 = e;
        float w0 = p[i0], w1 = p[i1];
        float inv = 1.f / (w0 + w1 + 1e-20f);
        w0 *= inv; w1 *= inv;
        int s0 = atomicAdd(&g_count[i0], 1);
        g_slot_token[i0 * MCAP + s0] = t;
        g_token_slot[t * 2 + 0] = i0 * MCAP + s0;
        g_token_w[t * 2 + 0] = w0;
        int s1 = atomicAdd(&g_count[i1], 1);
        g_slot_token[i1 * MCAP + s1] = t;
        g_token_slot[t * 2 + 1] = i1 * MCAP + s1;
        g_token_w[t * 2 + 1] = w1;
    }
}

// fp32 -> (bf16 hi, bf16 lo), vectorized by 4
__global__ void split_kernel(const float* __restrict__ src,
                             __nv_bfloat16* __restrict__ hi,
                             __nv_bfloat16* __restrict__ lo, int n4) {
    int i = blockIdx.x * blockDim.x + threadIdx.x;
    if (i >= n4) return;
    float4 v = ((const float4*)src)[i];
    __nv_bfloat16 h0 = __float2bfloat16(v.x);
    __nv_bfloat16 h1 = __float2bfloat16(v.y);
    __nv_bfloat16 h2 = __float2bfloat16(v.z);
    __nv_bfloat16 h3 = __float2bfloat16(v.w);
    __nv_bfloat16 l0 = __float2bfloat16(v.x - __bfloat162float(h0));
    __nv_bfloat16 l1 = __float2bfloat16(v.y - __bfloat162float(h1));
    __nv_bfloat16 l2 = __float2bfloat16(v.z - __bfloat162float(h2));
    __nv_bfloat16 l3 = __float2bfloat16(v.w - __bfloat162float(h3));
    uint32_t hp0 = ((uint32_t)__bfloat16_as_ushort(h1) << 16) | __bfloat16_as_ushort(h0);
    uint32_t hp1 = ((uint32_t)__bfloat16_as_ushort(h3) << 16) | __bfloat16_as_ushort(h2);
    uint32_t lp0 = ((uint32_t)__bfloat16_as_ushort(l1) << 16) | __bfloat16_as_ushort(l0);
    uint32_t lp1 = ((uint32_t)__bfloat16_as_ushort(l3) << 16) | __bfloat16_as_ushort(l2);
    ((uint2*)hi)[i] = make_uint2(hp0, hp1);
    ((uint2*)lo)[i] = make_uint2(lp0, lp1);
}

__global__ void combine_kernel(float* __restrict__ out) {
    int t = blockIdx.x;
    int tid = threadIdx.x;
    int s0 = g_token_slot[t * 2 + 0];
    int s1 = g_token_slot[t * 2 + 1];
    float w0 = g_token_w[t * 2 + 0];
    float w1 = g_token_w[t * 2 + 1];
    const float4* e0 = (const float4*)(g_eo + (size_t)s0 * DM);
    const float4* e1 = (const float4*)(g_eo + (size_t)s1 * DM);
    float4* o = (float4*)(out + (size_t)t * DM);
    float4 a = e0[tid], b = e1[tid], c = o[tid];
    c.x += w0 * a.x + w1 * b.x;
    c.y += w0 * a.y + w1 * b.y;
    c.z += w0 * a.z + w1 * b.z;
    c.w += w0 * a.w + w1 * b.w;
    o[tid] = c;
}

// ===================== mma.sync GEMM ========================================
// C[M,N] = A[M,K] @ B[N,K]^T + bias, fp32-accurate via bf16 hi/lo 3-MMA split.
// 128x256x32 block tile, 256 threads = 8 warps (2x4), warp tile 64x64.
// 3-stage cp.async pipeline, single __syncthreads per chunk.
#define BM 128
#define BN 256
#define BK 32
#define ROWB 80                          // bytes per smem row (64 used + 16 pad)
#define A_ARRB (128 * ROWB)              // 10240
#define B_ARRB (256 * ROWB)              // 20480
#define OFF_AH 0
#define OFF_AL A_ARRB
#define OFF_BH (2 * A_ARRB)
#define OFF_BL (2 * A_ARRB + B_ARRB)
#define STAGEB (2 * A_ARRB + 2 * B_ARRB) // 61440
#define NSTAGE 3
#define SMEM_TOTAL_GEMM (NSTAGE * STAGEB) // 184320

__global__ void __launch_bounds__(256)
mma_gemm(const __nv_bfloat16* __restrict__ Ah,
         const __nv_bfloat16* __restrict__ Al,
         const __nv_bfloat16* __restrict__ Bh,
         const __nv_bfloat16* __restrict__ Bl,
         const float* __restrict__ bias,
         float* __restrict__ Cf,
         __nv_bfloat16* __restrict__ Chi,
         __nv_bfloat16* __restrict__ Clo,
         const int* __restrict__ counts,
         const int* __restrict__ gather,
         int Mfixed, int N, int K,
         long long aStride,    // rows per expert in A (0 with gather)
         long long cStride,    // rows per expert in C
         int mode)             // 0: fp32 out; 1: relu + bf16 hi/lo out
{
    const int e = blockIdx.z;
    const int M = counts ? counts[e] : Mfixed;
    const int row0 = blockIdx.x * BM;
    if (row0 >= M) return;
    const int col0 = blockIdx.y * BN;

    extern __shared__ char smem[];
    const uint32_t sb = smem_u32(smem);
    const int tid = threadIdx.x;
    const int wid = tid >> 5;
    const int lane = tid & 31;

    // ---- cp.async setup: 12 x 16B per thread per chunk ---------------------
    const int lrow = tid >> 2;          // 0..63
    const int seg = tid & 3;            // 16B segment within 64B row
    int ra0 = row0 + lrow, ra1 = row0 + 64 + lrow;
    int ca0 = (ra0 < M) ? ra0 : (M - 1);
    int ca1 = (ra1 < M) ? ra1 : (M - 1);
    long long ga0 = (long long)e * aStride +
                    (gather ? (long long)gather[(size_t)e * MCAP + ca0] : (long long)ca0);
    long long ga1 = (long long)e * aStride +
                    (gather ? (long long)gather[(size_t)e * MCAP + ca1] : (long long)ca1);

    const char* pAh0 = (const char*)(Ah + (size_t)ga0 * K) + seg * 16;
    const char* pAh1 = (const char*)(Ah + (size_t)ga1 * K) + seg * 16;
    const char* pAl0 = (const char*)(Al + (size_t)ga0 * K) + seg * 16;
    const char* pAl1 = (const char*)(Al + (size_t)ga1 * K) + seg * 16;
    const char* pB[8];   // Bh rows lrow+{0,64,128,192}, then Bl same
#pragma unroll
    for (int j = 0; j < 4; j++) {
        long long gb = (long long)e * N + col0 + lrow + j * 64;
        pB[j]     = (const char*)(Bh + (size_t)gb * K) + seg * 16;
        pB[4 + j] = (const char*)(Bl + (size_t)gb * K) + seg * 16;
    }

    const uint32_t soA0 = lrow * ROWB + seg * 16;
    const uint32_t soA1 = (64 + lrow) * ROWB + seg * 16;

#define ISSUE(cc, st) do {                                                     \
    uint32_t _s = sb + (st) * STAGEB;                                          \
    size_t _g = (size_t)(cc) * 64;                                             \
    CPA(_s + OFF_AH + soA0, pAh0 + _g);                                        \
    CPA(_s + OFF_AH + soA1, pAh1 + _g);                                        \
    CPA(_s + OFF_AL + soA0, pAl0 + _g);                                        \
    CPA(_s + OFF_AL + soA1, pAl1 + _g);                                        \
    _Pragma("unroll")                                                          \
    for (int _j = 0; _j < 4; _j++)                                             \
        CPA(_s + OFF_BH + (_j * 64 + lrow) * ROWB + seg * 16, pB[_j] + _g);    \
    _Pragma("unroll")                                                          \
    for (int _j = 0; _j < 4; _j++)                                             \
        CPA(_s + OFF_BL + (_j * 64 + lrow) * ROWB + seg * 16, pB[4 + _j] + _g);\
    CP_COMMIT();                                                               \
} while (0)

    // ---- fragment addressing ----------------------------------------------
    const int warp_m = wid >> 2;        // 0..1
    const int warp_n = wid & 3;         // 0..3
    const int arow = (lane & 7) + ((lane >> 3) & 1) * 8;
    const int akk = ((lane >> 4) & 1) * 8;
    const int brow = (lane & 7) + ((lane >> 4) & 1) * 8;
    const int bkk = ((lane >> 3) & 1) * 8;

    float acc[4][8][4];
#pragma unroll
    for (int mi = 0; mi < 4; mi++)
#pragma unroll
        for (int ni = 0; ni < 8; ni++)
#pragma unroll
            for (int q = 0; q < 4; q++) acc[mi][ni][q] = 0.f;

    const int NC = K / BK;
    ISSUE(0, 0);
    ISSUE(1, 1);

    int st = 0, st_issue = 2;
    for (int c = 0; c < NC; c++) {
        CP_WAIT1();
        __syncthreads();
        if (c + 2 < NC) {
            ISSUE(c + 2, st_issue);
        } else {
            CP_COMMIT();               // keep wait_group invariant at tail
        }
        st_issue = (st_issue == NSTAGE - 1) ? 0 : st_issue + 1;

        const uint32_t sbase = sb + st * STAGEB;
#pragma unroll
        for (int ks = 0; ks < 2; ks++) {
            uint32_t ahi[4][4], alo[4][4], bhi[8][2], blo[8][2];
#pragma unroll
            for (int mi = 0; mi < 4; mi++) {
                uint32_t ad = sbase + OFF_AH +
                    (warp_m * 64 + mi * 16 + arow) * ROWB + (ks * 16 + akk) * 2;
                ldsm4(ahi[mi], ad);
                ldsm4(alo[mi], ad + A_ARRB);
            }
#pragma unroll
            for (int np = 0; np < 4; np++) {
                uint32_t bd = sbase + OFF_BH +
                    (warp_n * 64 + np * 16 + brow) * ROWB + (ks * 16 + bkk) * 2;
                uint32_t t0[4], t1[4];
                ldsm4(t0, bd);
                ldsm4(t1, bd + B_ARRB);
                bhi[np * 2][0] = t0[0]; bhi[np * 2][1] = t0[1];
                bhi[np * 2 + 1][0] = t0[2]; bhi[np * 2 + 1][1] = t0[3];
                blo[np * 2][0] = t1[0]; blo[np * 2][1] = t1[1];
                blo[np * 2 + 1][0] = t1[2]; blo[np * 2 + 1][1] = t1[3];
            }
#pragma unroll
            for (int mi = 0; mi < 4; mi++)
#pragma unroll
                for (int ni = 0; ni < 8; ni++) {
                    mma_bf16(acc[mi][ni], ahi[mi], bhi[ni]);
                    mma_bf16(acc[mi][ni], ahi[mi], blo[ni]);
                    mma_bf16(acc[mi][ni], alo[mi], bhi[ni]);
                }
        }
        st = (st == NSTAGE - 1) ? 0 : st + 1;
    }

    // ---- epilogue ----------------------------------------------------------
    const float* biasp = bias + (counts ? (size_t)e * N : 0);
    const int rin = lane >> 2;
    const int cpair = (lane & 3) * 2;

#pragma unroll
    for (int mi = 0; mi < 4; mi++) {
#pragma unroll
        for (int half = 0; half < 2; half++) {
            int rr = row0 + warp_m * 64 + mi * 16 + half * 8 + rin;
            if (rr >= M) continue;
            size_t crow = (size_t)e * cStride + rr;
#pragma unroll
            for (int ni = 0; ni < 8; ni++) {
                int col = col0 + warp_n * 64 + ni * 8 + cpair;
                float2 bv = *(const float2*)(biasp + col);
                float v0 = acc[mi][ni][half * 2 + 0] + bv.x;
                float v1 = acc[mi][ni][half * 2 + 1] + bv.y;
                if (mode) {
                    v0 = fmaxf(v0, 0.f);
                    v1 = fmaxf(v1, 0.f);
                    __nv_bfloat16 h0 = __float2bfloat16(v0);
                    __nv_bfloat16 h1 = __float2bfloat16(v1);
                    __nv_bfloat16 l0 = __float2bfloat16(v0 - __bfloat162float(h0));
                    __nv_bfloat16 l1 = __float2bfloat16(v1 - __bfloat162float(h1));
                    uint32_t hp = ((uint32_t)__bfloat16_as_ushort(h1) << 16) |
                                  __bfloat16_as_ushort(h0);
                    uint32_t lp = ((uint32_t)__bfloat16_as_ushort(l1) << 16) |
                                  __bfloat16_as_ushort(l0);
                    *(uint32_t*)(Chi + crow * N + col) = hp;
                    *(uint32_t*)(Clo + crow * N + col) = lp;
                } else {
                    *(float2*)(Cf + crow * N + col) = make_float2(v0, v1);
                }
            }
        }
    }
#undef ISSUE
}

// ===================== host launch ==========================================
extern "C" void kernel_launch(void* const* d_in, const int* in_sizes, int n_in,
                              void* d_out, int out_size) {
    const float* x      = (const float*)d_in[0];
    const float* gate_w = (const float*)d_in[1];
    const float* w1     = (const float*)d_in[2];
    const float* b1     = (const float*)d_in[3];
    const float* w2     = (const float*)d_in[4];
    const float* b2     = (const float*)d_in[5];
    const float* ws1    = (const float*)d_in[6];
    const float* bs1    = (const float*)d_in[7];
    const float* ws2    = (const float*)d_in[8];
    const float* bs2    = (const float*)d_in[9];
    float* out = (float*)d_out;

    int *count_p, *slot_p;
    __nv_bfloat16 *xh, *xl, *w1h, *w1l, *w2h, *w2l, *ws1h, *ws1l, *ws2h, *ws2l;
    __nv_bfloat16 *hh, *hl, *hsh, *hsl;
    float* eo;
    cudaGetSymbolAddress((void**)&count_p, g_count);
    cudaGetSymbolAddress((void**)&slot_p,  g_slot_token);
    cudaGetSymbolAddress((void**)&xh,  g_xh);   cudaGetSymbolAddress((void**)&xl,  g_xl);
    cudaGetSymbolAddress((void**)&w1h, g_w1h);  cudaGetSymbolAddress((void**)&w1l, g_w1l);
    cudaGetSymbolAddress((void**)&w2h, g_w2h);  cudaGetSymbolAddress((void**)&w2l, g_w2l);
    cudaGetSymbolAddress((void**)&ws1h, g_ws1h); cudaGetSymbolAddress((void**)&ws1l, g_ws1l);
    cudaGetSymbolAddress((void**)&ws2h, g_ws2h); cudaGetSymbolAddress((void**)&ws2l, g_ws2l);
    cudaGetSymbolAddress((void**)&hh,  g_hh);   cudaGetSymbolAddress((void**)&hl,  g_hl);
    cudaGetSymbolAddress((void**)&hsh, g_hsh);  cudaGetSymbolAddress((void**)&hsl, g_hsl);
    cudaGetSymbolAddress((void**)&eo,  g_eo);

    cudaFuncSetAttribute(mma_gemm, cudaFuncAttributeMaxDynamicSharedMemorySize,
                         SMEM_TOTAL_GEMM);

    // Launch order chosen so launch index 5 (ncu -s 5 -c 1) = routed GEMM1.
    zero_counts_kernel<<<1, 32>>>();                                   // 0
    gate_kernel<<<(T_TOKENS * 32) / 256, 256>>>(x, gate_w);            // 1
    {
        int n;
        n = T_TOKENS * DM; split_kernel<<<n / 4 / 256, 256>>>(x,  xh,  xl,  n / 4); // 2
        n = NE * DF * DM;  split_kernel<<<n / 4 / 256, 256>>>(w1, w1h, w1l, n / 4); // 3
        n = NE * DM * DF;  split_kernel<<<n / 4 / 256, 256>>>(w2, w2h, w2l, n / 4); // 4
    }
    // 5) routed GEMM1: h = relu(x[gather] @ w1^T + b1) -> bf16 hi/lo
    {
        dim3 grid(MCAP / BM, DF / BN, NE);
        mma_gemm<<<grid, 256, SMEM_TOTAL_GEMM>>>(
            xh, xl, w1h, w1l, b1, (float*)0, hh, hl,
            count_p, slot_p, 0, DF, DM, 0LL, (long long)MCAP, 1);
    }
    // 6) routed GEMM2: eo = h @ w2^T + b2 -> fp32
    {
        dim3 grid(MCAP / BM, DM / BN, NE);
        mma_gemm<<<grid, 256, SMEM_TOTAL_GEMM>>>(
            hh, hl, w2h, w2l, b2, eo, (__nv_bfloat16*)0, (__nv_bfloat16*)0,
            count_p, (const int*)0, 0, DM, DF,
            (long long)MCAP, (long long)MCAP, 0);
    }
    {
        int n;
        n = DF * DM; split_kernel<<<n / 4 / 256, 256>>>(ws1, ws1h, ws1l, n / 4); // 7
        n = DM * DF; split_kernel<<<n / 4 / 256, 256>>>(ws2, ws2h, ws2l, n / 4); // 8
    }
    // 9) shared GEMM1: hs = relu(x @ ws1^T + bs1) -> bf16 hi/lo
    {
        dim3 grid(T_TOKENS / BM, DF / BN, 1);
        mma_gemm<<<grid, 256, SMEM_TOTAL_GEMM>>>(
            xh, xl, ws1h, ws1l, bs1, (float*)0, hsh, hsl,
            (const int*)0, (const int*)0, T_TOKENS, DF, DM, 0LL, 0LL, 1);
    }
    // 10) shared GEMM2: out = hs @ ws2^T + bs2 -> fp32 (initializes out)
    {
        dim3 grid(T_TOKENS / BM, DM / BN, 1);
        mma_gemm<<<grid, 256, SMEM_TOTAL_GEMM>>>(
            hsh, hsl, ws2h, ws2l, bs2, out, (__nv_bfloat16*)0, (__nv_bfloat16*)0,
            (const int*)0, (const int*)0, T_TOKENS, DM, DF, 0LL, 0LL, 0);
    }
    // 11) combine routed into out
    combine_kernel<<<T_TOKENS, 256>>>(out);
}

// round 10
// speedup vs baseline: 3.6296x; 1.4040x over previous
#include <cuda_runtime.h>
#include <cuda_fp16.h>
#include <stdint.h>
#include <math.h>

#define T_TOKENS 8192
#define DM 1024
#define DF 2048
#define NE 8
#define MCAP 8192

// ===================== scratch (device globals) =============================
__device__ int   g_count[NE];
__device__ int   g_slot_token[NE * MCAP];
__device__ int   g_token_slot[T_TOKENS * 2];
__device__ float g_token_w[T_TOKENS * 2];

__device__ __half g_xh [(size_t)T_TOKENS * DM];
__device__ __half g_xl [(size_t)T_TOKENS * DM];
__device__ __half g_w1f[(size_t)NE * DF * DM];
__device__ __half g_w2f[(size_t)NE * DM * DF];
__device__ __half g_ws1f[(size_t)DF * DM];
__device__ __half g_ws2f[(size_t)DM * DF];
__device__ __half g_hh [(size_t)NE * MCAP * DF];
__device__ __half g_hl [(size_t)NE * MCAP * DF];
__device__ __half g_hsh[(size_t)T_TOKENS * DF];
__device__ __half g_hsl[(size_t)T_TOKENS * DF];
__device__ float g_eo[(size_t)NE * MCAP * DM];

// ===================== PTX helpers (plain sm_80+ features only) =============
__device__ __forceinline__ uint32_t smem_u32(const void* p) {
    uint32_t a;
    asm("{ .reg .u64 t; cvta.to.shared.u64 t, %1; cvt.u32.u64 %0, t; }"
        : "=r"(a) : "l"(p));
    return a;
}
__device__ __forceinline__ void ldsm4(uint32_t* r, uint32_t addr) {
    asm volatile("ldmatrix.sync.aligned.m8n8.x4.shared.b16 {%0,%1,%2,%3}, [%4];"
                 : "=r"(r[0]), "=r"(r[1]), "=r"(r[2]), "=r"(r[3]) : "r"(addr));
}
__device__ __forceinline__ void mma_f16(float* c, const uint32_t* a,
                                        const uint32_t* b) {
    asm volatile(
        "mma.sync.aligned.m16n8k16.row.col.f32.f16.f16.f32 "
        "{%0,%1,%2,%3}, {%4,%5,%6,%7}, {%8,%9}, {%0,%1,%2,%3};"
        : "+f"(c[0]), "+f"(c[1]), "+f"(c[2]), "+f"(c[3])
        : "r"(a[0]), "r"(a[1]), "r"(a[2]), "r"(a[3]), "r"(b[0]), "r"(b[1]));
}
#define CPA(sm, gp) \
    asm volatile("cp.async.cg.shared.global [%0], [%1], 16;" :: "r"(sm), "l"(gp))
#define CP_COMMIT() asm volatile("cp.async.commit_group;" ::: "memory")
#define CP_WAIT1()  asm volatile("cp.async.wait_group 1;" ::: "memory")

// ===================== small kernels ========================================
__global__ void zero_counts_kernel() {
    if (threadIdx.x < NE) g_count[threadIdx.x] = 0;
}

__global__ void gate_kernel(const float* __restrict__ x,
                            const float* __restrict__ gw) {
    int gtid = blockIdx.x * blockDim.x + threadIdx.x;
    int t = gtid >> 5;
    int lane = threadIdx.x & 31;
    if (t >= T_TOKENS) return;

    const float* xr = x + (size_t)t * DM;
    float acc[NE];
#pragma unroll
    for (int e = 0; e < NE; e++) acc[e] = 0.f;
    for (int d = lane; d < DM; d += 32) {
        float xv = xr[d];
#pragma unroll
        for (int e = 0; e < NE; e++) acc[e] += xv * gw[e * DM + d];
    }
#pragma unroll
    for (int e = 0; e < NE; e++)
#pragma unroll
        for (int o = 16; o > 0; o >>= 1)
            acc[e] += __shfl_xor_sync(0xffffffffu, acc[e], o);

    if (lane == 0) {
        float m = acc[0];
#pragma unroll
        for (int e = 1; e < NE; e++) m = fmaxf(m, acc[e]);
        float p[NE], s = 0.f;
#pragma unroll
        for (int e = 0; e < NE; e++) { p[e] = expf(acc[e] - m); s += p[e]; }
        float inv_s = 1.f / s;
#pragma unroll
        for (int e = 0; e < NE; e++) p[e] *= inv_s;
        int i0 = 0;
#pragma unroll
        for (int e = 1; e < NE; e++) if (p[e] > p[i0]) i0 = e;
        int i1 = (i0 == 0) ? 1 : 0;
#pragma unroll
        for (int e = 0; e < NE; e++)
            if (e != i0 && p[e] > p[i1]) i1 = e;
        float w0 = p[i0], w1 = p[i1];
        float inv = 1.f / (w0 + w1 + 1e-20f);
        w0 *= inv; w1 *= inv;
        int s0 = atomicAdd(&g_count[i0], 1);
        g_slot_token[i0 * MCAP + s0] = t;
        g_token_slot[t * 2 + 0] = i0 * MCAP + s0;
        g_token_w[t * 2 + 0] = w0;
        int s1 = atomicAdd(&g_count[i1], 1);
        g_slot_token[i1 * MCAP + s1] = t;
        g_token_slot[t * 2 + 1] = i1 * MCAP + s1;
        g_token_w[t * 2 + 1] = w1;
    }
}

// fp32 -> (fp16 hi, fp16 lo), vectorized by 4
__global__ void split_kernel(const float* __restrict__ src,
                             __half* __restrict__ hi,
                             __half* __restrict__ lo, int n4) {
    int i = blockIdx.x * blockDim.x + threadIdx.x;
    if (i >= n4) return;
    float4 v = ((const float4*)src)[i];
    __half h0 = __float2half_rn(v.x);
    __half h1 = __float2half_rn(v.y);
    __half h2 = __float2half_rn(v.z);
    __half h3 = __float2half_rn(v.w);
    __half l0 = __float2half_rn(v.x - __half2float(h0));
    __half l1 = __float2half_rn(v.y - __half2float(h1));
    __half l2 = __float2half_rn(v.z - __half2float(h2));
    __half l3 = __float2half_rn(v.w - __half2float(h3));
    uint32_t hp0 = ((uint32_t)__half_as_ushort(h1) << 16) | __half_as_ushort(h0);
    uint32_t hp1 = ((uint32_t)__half_as_ushort(h3) << 16) | __half_as_ushort(h2);
    uint32_t lp0 = ((uint32_t)__half_as_ushort(l1) << 16) | __half_as_ushort(l0);
    uint32_t lp1 = ((uint32_t)__half_as_ushort(l3) << 16) | __half_as_ushort(l2);
    ((uint2*)hi)[i] = make_uint2(hp0, hp1);
    ((uint2*)lo)[i] = make_uint2(lp0, lp1);
}

// fp32 -> fp16 single (weights), vectorized by 4
__global__ void tohalf_kernel(const float* __restrict__ src,
                              __half* __restrict__ dst, int n4) {
    int i = blockIdx.x * blockDim.x + threadIdx.x;
    if (i >= n4) return;
    float4 v = ((const float4*)src)[i];
    __half h0 = __float2half_rn(v.x);
    __half h1 = __float2half_rn(v.y);
    __half h2 = __float2half_rn(v.z);
    __half h3 = __float2half_rn(v.w);
    uint32_t p0 = ((uint32_t)__half_as_ushort(h1) << 16) | __half_as_ushort(h0);
    uint32_t p1 = ((uint32_t)__half_as_ushort(h3) << 16) | __half_as_ushort(h2);
    ((uint2*)dst)[i] = make_uint2(p0, p1);
}

__global__ void combine_kernel(float* __restrict__ out) {
    int t = blockIdx.x;
    int tid = threadIdx.x;
    int s0 = g_token_slot[t * 2 + 0];
    int s1 = g_token_slot[t * 2 + 1];
    float w0 = g_token_w[t * 2 + 0];
    float w1 = g_token_w[t * 2 + 1];
    const float4* e0 = (const float4*)(g_eo + (size_t)s0 * DM);
    const float4* e1 = (const float4*)(g_eo + (size_t)s1 * DM);
    float4* o = (float4*)(out + (size_t)t * DM);
    float4 a = e0[tid], b = e1[tid], c = o[tid];
    c.x += w0 * a.x + w1 * b.x;
    c.y += w0 * a.y + w1 * b.y;
    c.z += w0 * a.z + w1 * b.z;
    c.w += w0 * a.w + w1 * b.w;
    o[tid] = c;
}

// ===================== mma.sync GEMM ========================================
// C[M,N] = A[M,K] @ B[N,K]^T + bias.
// A = fp16 hi/lo split (2-term), B = single fp16 -> 2 MMAs per k-slab.
// 128x256x32 block tile, 256 threads = 8 warps (2x4), warp tile 64x64.
// 3-stage cp.async pipeline, single __syncthreads per chunk.
#define BM 128
#define BN 256
#define BK 32
#define ROWB 80                          // bytes per smem row (64 used + 16 pad)
#define A_ARRB (128 * ROWB)              // 10240
#define B_ARRB (256 * ROWB)              // 20480
#define OFF_AH 0
#define OFF_AL A_ARRB
#define OFF_B  (2 * A_ARRB)
#define STAGEB (2 * A_ARRB + B_ARRB)     // 40960
#define NSTAGE 3
#define SMEM_TOTAL_GEMM (NSTAGE * STAGEB) // 122880

__global__ void __launch_bounds__(256)
mma_gemm(const __half* __restrict__ Ah,
         const __half* __restrict__ Al,
         const __half* __restrict__ Bw,
         const float* __restrict__ bias,
         float* __restrict__ Cf,
         __half* __restrict__ Chi,
         __half* __restrict__ Clo,
         const int* __restrict__ counts,
         const int* __restrict__ gather,
         int Mfixed, int N, int K,
         long long aStride,    // rows per expert in A (0 with gather)
         long long cStride,    // rows per expert in C
         int mode)             // 0: fp32 out; 1: relu + fp16 hi/lo out
{
    const int e = blockIdx.z;
    const int M = counts ? counts[e] : Mfixed;
    const int row0 = blockIdx.x * BM;
    if (row0 >= M) return;
    const int col0 = blockIdx.y * BN;

    extern __shared__ char smem[];
    const uint32_t sb = smem_u32(smem);
    const int tid = threadIdx.x;
    const int wid = tid >> 5;
    const int lane = tid & 31;

    // ---- cp.async setup: 8 x 16B per thread per chunk ----------------------
    const int lrow = tid >> 2;          // 0..63
    const int seg = tid & 3;            // 16B segment within 64B row
    int ra0 = row0 + lrow, ra1 = row0 + 64 + lrow;
    int ca0 = (ra0 < M) ? ra0 : (M - 1);
    int ca1 = (ra1 < M) ? ra1 : (M - 1);
    long long ga0 = (long long)e * aStride +
                    (gather ? (long long)gather[(size_t)e * MCAP + ca0] : (long long)ca0);
    long long ga1 = (long long)e * aStride +
                    (gather ? (long long)gather[(size_t)e * MCAP + ca1] : (long long)ca1);

    const char* pAh0 = (const char*)(Ah + (size_t)ga0 * K) + seg * 16;
    const char* pAh1 = (const char*)(Ah + (size_t)ga1 * K) + seg * 16;
    const char* pAl0 = (const char*)(Al + (size_t)ga0 * K) + seg * 16;
    const char* pAl1 = (const char*)(Al + (size_t)ga1 * K) + seg * 16;
    const char* pB[4];   // B rows lrow+{0,64,128,192}
#pragma unroll
    for (int j = 0; j < 4; j++) {
        long long gb = (long long)e * N + col0 + lrow + j * 64;
        pB[j] = (const char*)(Bw + (size_t)gb * K) + seg * 16;
    }

    const uint32_t soA0 = lrow * ROWB + seg * 16;
    const uint32_t soA1 = (64 + lrow) * ROWB + seg * 16;

#define ISSUE(cc, st) do {                                                     \
    uint32_t _s = sb + (st) * STAGEB;                                          \
    size_t _g = (size_t)(cc) * 64;                                             \
    CPA(_s + OFF_AH + soA0, pAh0 + _g);                                        \
    CPA(_s + OFF_AH + soA1, pAh1 + _g);                                        \
    CPA(_s + OFF_AL + soA0, pAl0 + _g);                                        \
    CPA(_s + OFF_AL + soA1, pAl1 + _g);                                        \
    _Pragma("unroll")                                                          \
    for (int _j = 0; _j < 4; _j++)                                             \
        CPA(_s + OFF_B + (_j * 64 + lrow) * ROWB + seg * 16, pB[_j] + _g);     \
    CP_COMMIT();                                                               \
} while (0)

    // ---- fragment addressing ----------------------------------------------
    const int warp_m = wid >> 2;        // 0..1
    const int warp_n = wid & 3;         // 0..3
    const int arow = (lane & 7) + ((lane >> 3) & 1) * 8;
    const int akk = ((lane >> 4) & 1) * 8;
    const int brow = (lane & 7) + ((lane >> 4) & 1) * 8;
    const int bkk = ((lane >> 3) & 1) * 8;

    float acc[4][8][4];
#pragma unroll
    for (int mi = 0; mi < 4; mi++)
#pragma unroll
        for (int ni = 0; ni < 8; ni++)
#pragma unroll
            for (int q = 0; q < 4; q++) acc[mi][ni][q] = 0.f;

    const int NC = K / BK;
    ISSUE(0, 0);
    ISSUE(1, 1);

    int st = 0, st_issue = 2;
    for (int c = 0; c < NC; c++) {
        CP_WAIT1();
        __syncthreads();
        if (c + 2 < NC) {
            ISSUE(c + 2, st_issue);
        } else {
            CP_COMMIT();               // keep wait_group invariant at tail
        }
        st_issue = (st_issue == NSTAGE - 1) ? 0 : st_issue + 1;

        const uint32_t sbase = sb + st * STAGEB;
#pragma unroll
        for (int ks = 0; ks < 2; ks++) {
            uint32_t ahi[4][4], alo[4][4], bfr[8][2];
#pragma unroll
            for (int mi = 0; mi < 4; mi++) {
                uint32_t ad = sbase + OFF_AH +
                    (warp_m * 64 + mi * 16 + arow) * ROWB + (ks * 16 + akk) * 2;
                ldsm4(ahi[mi], ad);
                ldsm4(alo[mi], ad + A_ARRB);
            }
#pragma unroll
            for (int np = 0; np < 4; np++) {
                uint32_t bd = sbase + OFF_B +
                    (warp_n * 64 + np * 16 + brow) * ROWB + (ks * 16 + bkk) * 2;
                uint32_t t0[4];
                ldsm4(t0, bd);
                bfr[np * 2][0] = t0[0]; bfr[np * 2][1] = t0[1];
                bfr[np * 2 + 1][0] = t0[2]; bfr[np * 2 + 1][1] = t0[3];
            }
#pragma unroll
            for (int mi = 0; mi < 4; mi++)
#pragma unroll
                for (int ni = 0; ni < 8; ni++) {
                    mma_f16(acc[mi][ni], ahi[mi], bfr[ni]);
                    mma_f16(acc[mi][ni], alo[mi], bfr[ni]);
                }
        }
        st = (st == NSTAGE - 1) ? 0 : st + 1;
    }

    // ---- epilogue ----------------------------------------------------------
    const float* biasp = bias + (counts ? (size_t)e * N : 0);
    const int rin = lane >> 2;
    const int cpair = (lane & 3) * 2;

#pragma unroll
    for (int mi = 0; mi < 4; mi++) {
#pragma unroll
        for (int half = 0; half < 2; half++) {
            int rr = row0 + warp_m * 64 + mi * 16 + half * 8 + rin;
            if (rr >= M) continue;
            size_t crow = (size_t)e * cStride + rr;
#pragma unroll
            for (int ni = 0; ni < 8; ni++) {
                int col = col0 + warp_n * 64 + ni * 8 + cpair;
                float2 bv = *(const float2*)(biasp + col);
                float v0 = acc[mi][ni][half * 2 + 0] + bv.x;
                float v1 = acc[mi][ni][half * 2 + 1] + bv.y;
                if (mode) {
                    v0 = fmaxf(v0, 0.f);
                    v1 = fmaxf(v1, 0.f);
                    __half h0 = __float2half_rn(v0);
                    __half h1 = __float2half_rn(v1);
                    __half l0 = __float2half_rn(v0 - __half2float(h0));
                    __half l1 = __float2half_rn(v1 - __half2float(h1));
                    uint32_t hp = ((uint32_t)__half_as_ushort(h1) << 16) |
                                  __half_as_ushort(h0);
                    uint32_t lp = ((uint32_t)__half_as_ushort(l1) << 16) |
                                  __half_as_ushort(l0);
                    *(uint32_t*)(Chi + crow * N + col) = hp;
                    *(uint32_t*)(Clo + crow * N + col) = lp;
                } else {
                    *(float2*)(Cf + crow * N + col) = make_float2(v0, v1);
                }
            }
        }
    }
#undef ISSUE
}

// ===================== host launch ==========================================
extern "C" void kernel_launch(void* const* d_in, const int* in_sizes, int n_in,
                              void* d_out, int out_size) {
    const float* x      = (const float*)d_in[0];
    const float* gate_w = (const float*)d_in[1];
    const float* w1     = (const float*)d_in[2];
    const float* b1     = (const float*)d_in[3];
    const float* w2     = (const float*)d_in[4];
    const float* b2     = (const float*)d_in[5];
    const float* ws1    = (const float*)d_in[6];
    const float* bs1    = (const float*)d_in[7];
    const float* ws2    = (const float*)d_in[8];
    const float* bs2    = (const float*)d_in[9];
    float* out = (float*)d_out;

    int *count_p, *slot_p;
    __half *xh, *xl, *w1f, *w2f, *ws1f, *ws2f, *hh, *hl, *hsh, *hsl;
    float* eo;
    cudaGetSymbolAddress((void**)&count_p, g_count);
    cudaGetSymbolAddress((void**)&slot_p,  g_slot_token);
    cudaGetSymbolAddress((void**)&xh,  g_xh);   cudaGetSymbolAddress((void**)&xl,  g_xl);
    cudaGetSymbolAddress((void**)&w1f, g_w1f);  cudaGetSymbolAddress((void**)&w2f, g_w2f);
    cudaGetSymbolAddress((void**)&ws1f, g_ws1f); cudaGetSymbolAddress((void**)&ws2f, g_ws2f);
    cudaGetSymbolAddress((void**)&hh,  g_hh);   cudaGetSymbolAddress((void**)&hl,  g_hl);
    cudaGetSymbolAddress((void**)&hsh, g_hsh);  cudaGetSymbolAddress((void**)&hsl, g_hsl);
    cudaGetSymbolAddress((void**)&eo,  g_eo);

    cudaFuncSetAttribute(mma_gemm, cudaFuncAttributeMaxDynamicSharedMemorySize,
                         SMEM_TOTAL_GEMM);

    zero_counts_kernel<<<1, 32>>>();
    gate_kernel<<<(T_TOKENS * 32) / 256, 256>>>(x, gate_w);
    {
        int n;
        n = T_TOKENS * DM; split_kernel<<<n / 4 / 256, 256>>>(x, xh, xl, n / 4);
        n = NE * DF * DM;  tohalf_kernel<<<n / 4 / 256, 256>>>(w1, w1f, n / 4);
        n = NE * DM * DF;  tohalf_kernel<<<n / 4 / 256, 256>>>(w2, w2f, n / 4);
        n = DF * DM;       tohalf_kernel<<<n / 4 / 256, 256>>>(ws1, ws1f, n / 4);
        n = DM * DF;       tohalf_kernel<<<n / 4 / 256, 256>>>(ws2, ws2f, n / 4);
    }
    // routed GEMM1: h = relu(x[gather] @ w1^T + b1) -> fp16 hi/lo
    {
        dim3 grid(MCAP / BM, DF / BN, NE);
        mma_gemm<<<grid, 256, SMEM_TOTAL_GEMM>>>(
            xh, xl, w1f, b1, (float*)0, hh, hl,
            count_p, slot_p, 0, DF, DM, 0LL, (long long)MCAP, 1);
    }
    // routed GEMM2: eo = h @ w2^T + b2 -> fp32
    {
        dim3 grid(MCAP / BM, DM / BN, NE);
        mma_gemm<<<grid, 256, SMEM_TOTAL_GEMM>>>(
            hh, hl, w2f, b2, eo, (__half*)0, (__half*)0,
            count_p, (const int*)0, 0, DM, DF,
            (long long)MCAP, (long long)MCAP, 0);
    }
    // shared GEMM1: hs = relu(x @ ws1^T + bs1) -> fp16 hi/lo
    {
        dim3 grid(T_TOKENS / BM, DF / BN, 1);
        mma_gemm<<<grid, 256, SMEM_TOTAL_GEMM>>>(
            xh, xl, ws1f, bs1, (float*)0, hsh, hsl,
            (const int*)0, (const int*)0, T_TOKENS, DF, DM, 0LL, 0LL, 1);
    }
    // shared GEMM2: out = hs @ ws2^T + bs2 -> fp32 (initializes out)
    {
        dim3 grid(T_TOKENS / BM, DM / BN, 1);
        mma_gemm<<<grid, 256, SMEM_TOTAL_GEMM>>>(
            hsh, hsl, ws2f, bs2, out, (__half*)0, (__half*)0,
            (const int*)0, (const int*)0, T_TOKENS, DM, DF, 0LL, 0LL, 0);
    }
    // combine routed into out
    combine_kernel<<<T_TOKENS, 256>>>(out);
}

// round 11
// speedup vs baseline: 3.7917x; 1.0447x over previous
#include <cuda_runtime.h>
#include <cuda_fp16.h>
#include <stdint.h>
#include <math.h>

#define T_TOKENS 8192
#define DM 1024
#define DF 2048
#define NE 8
#define MCAP 8192

// ===================== scratch (device globals) =============================
__device__ int   g_count[NE];
__device__ int   g_slot_token[NE * MCAP];
__device__ int   g_token_slot[T_TOKENS * 2];
__device__ float g_token_w[T_TOKENS * 2];

__device__ __half g_xh [(size_t)T_TOKENS * DM];
__device__ __half g_xl [(size_t)T_TOKENS * DM];
__device__ __half g_w1f[(size_t)NE * DF * DM];
__device__ __half g_w2f[(size_t)NE * DM * DF];
__device__ __half g_ws1f[(size_t)DF * DM];
__device__ __half g_ws2f[(size_t)DM * DF];
__device__ __half g_hh [(size_t)NE * MCAP * DF];
__device__ __half g_hsh[(size_t)T_TOKENS * DF];
__device__ float g_eo[(size_t)NE * MCAP * DM];

// ===================== PTX helpers (plain sm_80+ features only) =============
__device__ __forceinline__ uint32_t smem_u32(const void* p) {
    uint32_t a;
    asm("{ .reg .u64 t; cvta.to.shared.u64 t, %1; cvt.u32.u64 %0, t; }"
        : "=r"(a) : "l"(p));
    return a;
}
__device__ __forceinline__ void ldsm4(uint32_t* r, uint32_t addr) {
    asm volatile("ldmatrix.sync.aligned.m8n8.x4.shared.b16 {%0,%1,%2,%3}, [%4];"
                 : "=r"(r[0]), "=r"(r[1]), "=r"(r[2]), "=r"(r[3]) : "r"(addr));
}
__device__ __forceinline__ void mma_f16(float* c, const uint32_t* a,
                                        const uint32_t* b) {
    asm volatile(
        "mma.sync.aligned.m16n8k16.row.col.f32.f16.f16.f32 "
        "{%0,%1,%2,%3}, {%4,%5,%6,%7}, {%8,%9}, {%0,%1,%2,%3};"
        : "+f"(c[0]), "+f"(c[1]), "+f"(c[2]), "+f"(c[3])
        : "r"(a[0]), "r"(a[1]), "r"(a[2]), "r"(a[3]), "r"(b[0]), "r"(b[1]));
}
#define CPA(sm, gp) \
    asm volatile("cp.async.cg.shared.global [%0], [%1], 16;" :: "r"(sm), "l"(gp))
#define CP_COMMIT() asm volatile("cp.async.commit_group;" ::: "memory")
#define CP_WAIT1()  asm volatile("cp.async.wait_group 1;" ::: "memory")

// ===================== small kernels ========================================
__global__ void zero_counts_kernel() {
    if (threadIdx.x < NE) g_count[threadIdx.x] = 0;
}

__global__ void gate_kernel(const float* __restrict__ x,
                            const float* __restrict__ gw) {
    int gtid = blockIdx.x * blockDim.x + threadIdx.x;
    int t = gtid >> 5;
    int lane = threadIdx.x & 31;
    if (t >= T_TOKENS) return;

    const float* xr = x + (size_t)t * DM;
    float acc[NE];
#pragma unroll
    for (int e = 0; e < NE; e++) acc[e] = 0.f;
    for (int d = lane; d < DM; d += 32) {
        float xv = xr[d];
#pragma unroll
        for (int e = 0; e < NE; e++) acc[e] += xv * gw[e * DM + d];
    }
#pragma unroll
    for (int e = 0; e < NE; e++)
#pragma unroll
        for (int o = 16; o > 0; o >>= 1)
            acc[e] += __shfl_xor_sync(0xffffffffu, acc[e], o);

    if (lane == 0) {
        float m = acc[0];
#pragma unroll
        for (int e = 1; e < NE; e++) m = fmaxf(m, acc[e]);
        float p[NE], s = 0.f;
#pragma unroll
        for (int e = 0; e < NE; e++) { p[e] = expf(acc[e] - m); s += p[e]; }
        float inv_s = 1.f / s;
#pragma unroll
        for (int e = 0; e < NE; e++) p[e] *= inv_s;
        int i0 = 0;
#pragma unroll
        for (int e = 1; e < NE; e++) if (p[e] > p[i0]) i0 = e;
        int i1 = (i0 == 0) ? 1 : 0;
#pragma unroll
        for (int e = 0; e < NE; e++)
            if (e != i0 && p[e] > p[i1]) i1 = e;
        float w0 = p[i0], w1 = p[i1];
        float inv = 1.f / (w0 + w1 + 1e-20f);
        w0 *= inv; w1 *= inv;
        int s0 = atomicAdd(&g_count[i0], 1);
        g_slot_token[i0 * MCAP + s0] = t;
        g_token_slot[t * 2 + 0] = i0 * MCAP + s0;
        g_token_w[t * 2 + 0] = w0;
        int s1 = atomicAdd(&g_count[i1], 1);
        g_slot_token[i1 * MCAP + s1] = t;
        g_token_slot[t * 2 + 1] = i1 * MCAP + s1;
        g_token_w[t * 2 + 1] = w1;
    }
}

// fp32 -> (fp16 hi, fp16 lo), vectorized by 4
__global__ void split_kernel(const float* __restrict__ src,
                             __half* __restrict__ hi,
                             __half* __restrict__ lo, int n4) {
    int i = blockIdx.x * blockDim.x + threadIdx.x;
    if (i >= n4) return;
    float4 v = ((const float4*)src)[i];
    __half h0 = __float2half_rn(v.x);
    __half h1 = __float2half_rn(v.y);
    __half h2 = __float2half_rn(v.z);
    __half h3 = __float2half_rn(v.w);
    __half l0 = __float2half_rn(v.x - __half2float(h0));
    __half l1 = __float2half_rn(v.y - __half2float(h1));
    __half l2 = __float2half_rn(v.z - __half2float(h2));
    __half l3 = __float2half_rn(v.w - __half2float(h3));
    uint32_t hp0 = ((uint32_t)__half_as_ushort(h1) << 16) | __half_as_ushort(h0);
    uint32_t hp1 = ((uint32_t)__half_as_ushort(h3) << 16) | __half_as_ushort(h2);
    uint32_t lp0 = ((uint32_t)__half_as_ushort(l1) << 16) | __half_as_ushort(l0);
    uint32_t lp1 = ((uint32_t)__half_as_ushort(l3) << 16) | __half_as_ushort(l2);
    ((uint2*)hi)[i] = make_uint2(hp0, hp1);
    ((uint2*)lo)[i] = make_uint2(lp0, lp1);
}

// fp32 -> fp16 single (weights), vectorized by 4
__global__ void tohalf_kernel(const float* __restrict__ src,
                              __half* __restrict__ dst, int n4) {
    int i = blockIdx.x * blockDim.x + threadIdx.x;
    if (i >= n4) return;
    float4 v = ((const float4*)src)[i];
    __half h0 = __float2half_rn(v.x);
    __half h1 = __float2half_rn(v.y);
    __half h2 = __float2half_rn(v.z);
    __half h3 = __float2half_rn(v.w);
    uint32_t p0 = ((uint32_t)__half_as_ushort(h1) << 16) | __half_as_ushort(h0);
    uint32_t p1 = ((uint32_t)__half_as_ushort(h3) << 16) | __half_as_ushort(h2);
    ((uint2*)dst)[i] = make_uint2(p0, p1);
}

__global__ void combine_kernel(float* __restrict__ out) {
    int t = blockIdx.x;
    int tid = threadIdx.x;
    int s0 = g_token_slot[t * 2 + 0];
    int s1 = g_token_slot[t * 2 + 1];
    float w0 = g_token_w[t * 2 + 0];
    float w1 = g_token_w[t * 2 + 1];
    const float4* e0 = (const float4*)(g_eo + (size_t)s0 * DM);
    const float4* e1 = (const float4*)(g_eo + (size_t)s1 * DM);
    float4* o = (float4*)(out + (size_t)t * DM);
    float4 a = e0[tid], b = e1[tid], c = o[tid];
    c.x += w0 * a.x + w1 * b.x;
    c.y += w0 * a.y + w1 * b.y;
    c.z += w0 * a.z + w1 * b.z;
    c.w += w0 * a.w + w1 * b.w;
    o[tid] = c;
}

// ===================== mma.sync GEMM ========================================
// C[M,N] = A[M,K] @ B[N,K]^T + bias.
// A = fp16 hi (+ optional lo term when Al != 0), B = single fp16.
// 128x256x32 block tile, 256 threads = 8 warps (2x4), warp tile 64x64.
// 3-stage cp.async pipeline, single __syncthreads per chunk.
#define BM 128
#define BN 256
#define BK 32
#define ROWB 80                          // bytes per smem row (64 used + 16 pad)
#define A_ARRB (128 * ROWB)              // 10240
#define B_ARRB (256 * ROWB)              // 20480
#define OFF_AH 0
#define OFF_AL A_ARRB
#define OFF_B  (2 * A_ARRB)
#define STAGEB (2 * A_ARRB + B_ARRB)     // 40960
#define NSTAGE 3
#define SMEM_TOTAL_GEMM (NSTAGE * STAGEB) // 122880

__global__ void __launch_bounds__(256)
mma_gemm(const __half* __restrict__ Ah,
         const __half* __restrict__ Al,   // may be null: single-term A
         const __half* __restrict__ Bw,
         const float* __restrict__ bias,
         float* __restrict__ Cf,
         __half* __restrict__ Chalf,
         const int* __restrict__ counts,
         const int* __restrict__ gather,
         int Mfixed, int N, int K,
         long long aStride,    // rows per expert in A (0 with gather)
         long long cStride,    // rows per expert in C
         int mode)             // 0: fp32 out; 1: relu + fp16 out
{
    const int e = blockIdx.z;
    const int M = counts ? counts[e] : Mfixed;
    const int row0 = blockIdx.x * BM;
    if (row0 >= M) return;
    const int col0 = blockIdx.y * BN;

    extern __shared__ char smem[];
    const uint32_t sb = smem_u32(smem);
    const int tid = threadIdx.x;
    const int wid = tid >> 5;
    const int lane = tid & 31;
    const bool twoA = (Al != 0);

    // ---- cp.async setup ----------------------------------------------------
    const int lrow = tid >> 2;          // 0..63
    const int seg = tid & 3;            // 16B segment within 64B row
    int ra0 = row0 + lrow, ra1 = row0 + 64 + lrow;
    int ca0 = (ra0 < M) ? ra0 : (M - 1);
    int ca1 = (ra1 < M) ? ra1 : (M - 1);
    long long ga0 = (long long)e * aStride +
                    (gather ? (long long)gather[(size_t)e * MCAP + ca0] : (long long)ca0);
    long long ga1 = (long long)e * aStride +
                    (gather ? (long long)gather[(size_t)e * MCAP + ca1] : (long long)ca1);

    const char* pAh0 = (const char*)(Ah + (size_t)ga0 * K) + seg * 16;
    const char* pAh1 = (const char*)(Ah + (size_t)ga1 * K) + seg * 16;
    const char* pAl0 = 0;
    const char* pAl1 = 0;
    if (twoA) {
        pAl0 = (const char*)(Al + (size_t)ga0 * K) + seg * 16;
        pAl1 = (const char*)(Al + (size_t)ga1 * K) + seg * 16;
    }
    const char* pB[4];   // B rows lrow+{0,64,128,192}
#pragma unroll
    for (int j = 0; j < 4; j++) {
        long long gb = (long long)e * N + col0 + lrow + j * 64;
        pB[j] = (const char*)(Bw + (size_t)gb * K) + seg * 16;
    }

    const uint32_t soA0 = lrow * ROWB + seg * 16;
    const uint32_t soA1 = (64 + lrow) * ROWB + seg * 16;

#define ISSUE(cc, st) do {                                                     \
    uint32_t _s = sb + (st) * STAGEB;                                          \
    size_t _g = (size_t)(cc) * 64;                                             \
    CPA(_s + OFF_AH + soA0, pAh0 + _g);                                        \
    CPA(_s + OFF_AH + soA1, pAh1 + _g);                                        \
    if (twoA) {                                                                \
        CPA(_s + OFF_AL + soA0, pAl0 + _g);                                    \
        CPA(_s + OFF_AL + soA1, pAl1 + _g);                                    \
    }                                                                          \
    _Pragma("unroll")                                                          \
    for (int _j = 0; _j < 4; _j++)                                             \
        CPA(_s + OFF_B + (_j * 64 + lrow) * ROWB + seg * 16, pB[_j] + _g);     \
    CP_COMMIT();                                                               \
} while (0)

    // ---- fragment addressing ----------------------------------------------
    const int warp_m = wid >> 2;        // 0..1
    const int warp_n = wid & 3;         // 0..3
    const int arow = (lane & 7) + ((lane >> 3) & 1) * 8;
    const int akk = ((lane >> 4) & 1) * 8;
    const int brow = (lane & 7) + ((lane >> 4) & 1) * 8;
    const int bkk = ((lane >> 3) & 1) * 8;

    float acc[4][8][4];
#pragma unroll
    for (int mi = 0; mi < 4; mi++)
#pragma unroll
        for (int ni = 0; ni < 8; ni++)
#pragma unroll
            for (int q = 0; q < 4; q++) acc[mi][ni][q] = 0.f;

    const int NC = K / BK;
    ISSUE(0, 0);
    ISSUE(1, 1);

    int st = 0, st_issue = 2;
    for (int c = 0; c < NC; c++) {
        CP_WAIT1();
        __syncthreads();
        if (c + 2 < NC) {
            ISSUE(c + 2, st_issue);
        } else {
            CP_COMMIT();               // keep wait_group invariant at tail
        }
        st_issue = (st_issue == NSTAGE - 1) ? 0 : st_issue + 1;

        const uint32_t sbase = sb + st * STAGEB;
#pragma unroll
        for (int ks = 0; ks < 2; ks++) {
            uint32_t ahi[4][4], alo[4][4], bfr[8][2];
#pragma unroll
            for (int mi = 0; mi < 4; mi++) {
                uint32_t ad = sbase + OFF_AH +
                    (warp_m * 64 + mi * 16 + arow) * ROWB + (ks * 16 + akk) * 2;
                ldsm4(ahi[mi], ad);
                if (twoA) ldsm4(alo[mi], ad + A_ARRB);
            }
#pragma unroll
            for (int np = 0; np < 4; np++) {
                uint32_t bd = sbase + OFF_B +
                    (warp_n * 64 + np * 16 + brow) * ROWB + (ks * 16 + bkk) * 2;
                uint32_t t0[4];
                ldsm4(t0, bd);
                bfr[np * 2][0] = t0[0]; bfr[np * 2][1] = t0[1];
                bfr[np * 2 + 1][0] = t0[2]; bfr[np * 2 + 1][1] = t0[3];
            }
#pragma unroll
            for (int mi = 0; mi < 4; mi++)
#pragma unroll
                for (int ni = 0; ni < 8; ni++) {
                    mma_f16(acc[mi][ni], ahi[mi], bfr[ni]);
                    if (twoA) mma_f16(acc[mi][ni], alo[mi], bfr[ni]);
                }
        }
        st = (st == NSTAGE - 1) ? 0 : st + 1;
    }

    // ---- epilogue ----------------------------------------------------------
    const float* biasp = bias + (counts ? (size_t)e * N : 0);
    const int rin = lane >> 2;
    const int cpair = (lane & 3) * 2;

#pragma unroll
    for (int mi = 0; mi < 4; mi++) {
#pragma unroll
        for (int half = 0; half < 2; half++) {
            int rr = row0 + warp_m * 64 + mi * 16 + half * 8 + rin;
            if (rr >= M) continue;
            size_t crow = (size_t)e * cStride + rr;
#pragma unroll
            for (int ni = 0; ni < 8; ni++) {
                int col = col0 + warp_n * 64 + ni * 8 + cpair;
                float2 bv = *(const float2*)(biasp + col);
                float v0 = acc[mi][ni][half * 2 + 0] + bv.x;
                float v1 = acc[mi][ni][half * 2 + 1] + bv.y;
                if (mode) {
                    v0 = fmaxf(v0, 0.f);
                    v1 = fmaxf(v1, 0.f);
                    __half h0 = __float2half_rn(v0);
                    __half h1 = __float2half_rn(v1);
                    uint32_t hp = ((uint32_t)__half_as_ushort(h1) << 16) |
                                  __half_as_ushort(h0);
                    *(uint32_t*)(Chalf + crow * N + col) = hp;
                } else {
                    *(float2*)(Cf + crow * N + col) = make_float2(v0, v1);
                }
            }
        }
    }
#undef ISSUE
}

// ===================== host launch ==========================================
extern "C" void kernel_launch(void* const* d_in, const int* in_sizes, int n_in,
                              void* d_out, int out_size) {
    const float* x      = (const float*)d_in[0];
    const float* gate_w = (const float*)d_in[1];
    const float* w1     = (const float*)d_in[2];
    const float* b1     = (const float*)d_in[3];
    const float* w2     = (const float*)d_in[4];
    const float* b2     = (const float*)d_in[5];
    const float* ws1    = (const float*)d_in[6];
    const float* bs1    = (const float*)d_in[7];
    const float* ws2    = (const float*)d_in[8];
    const float* bs2    = (const float*)d_in[9];
    float* out = (float*)d_out;

    int *count_p, *slot_p;
    __half *xh, *xl, *w1f, *w2f, *ws1f, *ws2f, *hh, *hsh;
    float* eo;
    cudaGetSymbolAddress((void**)&count_p, g_count);
    cudaGetSymbolAddress((void**)&slot_p,  g_slot_token);
    cudaGetSymbolAddress((void**)&xh,  g_xh);   cudaGetSymbolAddress((void**)&xl,  g_xl);
    cudaGetSymbolAddress((void**)&w1f, g_w1f);  cudaGetSymbolAddress((void**)&w2f, g_w2f);
    cudaGetSymbolAddress((void**)&ws1f, g_ws1f); cudaGetSymbolAddress((void**)&ws2f, g_ws2f);
    cudaGetSymbolAddress((void**)&hh,  g_hh);   cudaGetSymbolAddress((void**)&hsh, g_hsh);
    cudaGetSymbolAddress((void**)&eo,  g_eo);

    cudaFuncSetAttribute(mma_gemm, cudaFuncAttributeMaxDynamicSharedMemorySize,
                         SMEM_TOTAL_GEMM);

    zero_counts_kernel<<<1, 32>>>();
    gate_kernel<<<(T_TOKENS * 32) / 256, 256>>>(x, gate_w);
    {
        int n;
        n = T_TOKENS * DM; split_kernel<<<n / 4 / 256, 256>>>(x, xh, xl, n / 4);
        n = NE * DF * DM;  tohalf_kernel<<<n / 4 / 256, 256>>>(w1, w1f, n / 4);
        n = NE * DM * DF;  tohalf_kernel<<<n / 4 / 256, 256>>>(w2, w2f, n / 4);
        n = DF * DM;       tohalf_kernel<<<n / 4 / 256, 256>>>(ws1, ws1f, n / 4);
        n = DM * DF;       tohalf_kernel<<<n / 4 / 256, 256>>>(ws2, ws2f, n / 4);
    }
    // routed GEMM1 (2-term A): h = relu(x[gather] @ w1^T + b1) -> fp16
    {
        dim3 grid(MCAP / BM, DF / BN, NE);
        mma_gemm<<<grid, 256, SMEM_TOTAL_GEMM>>>(
            xh, xl, w1f, b1, (float*)0, hh,
            count_p, slot_p, 0, DF, DM, 0LL, (long long)MCAP, 1);
    }
    // routed GEMM2 (1-term A): eo = h @ w2^T + b2 -> fp32
    {
        dim3 grid(MCAP / BM, DM / BN, NE);
        mma_gemm<<<grid, 256, SMEM_TOTAL_GEMM>>>(
            hh, (const __half*)0, w2f, b2, eo, (__half*)0,
            count_p, (const int*)0, 0, DM, DF,
            (long long)MCAP, (long long)MCAP, 0);
    }
    // shared GEMM1 (2-term A): hs = relu(x @ ws1^T + bs1) -> fp16
    {
        dim3 grid(T_TOKENS / BM, DF / BN, 1);
        mma_gemm<<<grid, 256, SMEM_TOTAL_GEMM>>>(
            xh, xl, ws1f, bs1, (float*)0, hsh,
            (const int*)0, (const int*)0, T_TOKENS, DF, DM, 0LL, 0LL, 1);
    }
    // shared GEMM2 (1-term A): out = hs @ ws2^T + bs2 -> fp32 (initializes out)
    {
        dim3 grid(T_TOKENS / BM, DM / BN, 1);
        mma_gemm<<<grid, 256, SMEM_TOTAL_GEMM>>>(
            hsh, (const __half*)0, ws2f, bs2, out, (__half*)0,
            (const int*)0, (const int*)0, T_TOKENS, DM, DF, 0LL, 0LL, 0);
    }
    // combine routed into out
    combine_kernel<<<T_TOKENS, 256>>>(out);
}

// round 12
// speedup vs baseline: 5.6305x; 1.4850x over previous
#include <cuda_runtime.h>
#include <cuda_fp16.h>
#include <stdint.h>
#include <math.h>

#define T_TOKENS 8192
#define DM 1024
#define DF 2048
#define NE 8
#define MCAP 8192

// ===================== scratch (device globals) =============================
__device__ int   g_count[NE];
__device__ int   g_slot_token[NE * MCAP];
__device__ int   g_token_slot[T_TOKENS * 2];
__device__ float g_token_w[T_TOKENS * 2];

__device__ __half g_xf [(size_t)T_TOKENS * DM];
__device__ __half g_w1f[(size_t)NE * DF * DM];
__device__ __half g_w2f[(size_t)NE * DM * DF];
__device__ __half g_ws1f[(size_t)DF * DM];
__device__ __half g_ws2f[(size_t)DM * DF];
__device__ __half g_hh [(size_t)NE * MCAP * DF];
__device__ __half g_hsh[(size_t)T_TOKENS * DF];
__device__ float g_eo[(size_t)NE * MCAP * DM];

// ===================== PTX helpers (plain sm_80+ features only) =============
__device__ __forceinline__ uint32_t smem_u32(const void* p) {
    uint32_t a;
    asm("{ .reg .u64 t; cvta.to.shared.u64 t, %1; cvt.u32.u64 %0, t; }"
        : "=r"(a) : "l"(p));
    return a;
}
__device__ __forceinline__ void ldsm4(uint32_t* r, uint32_t addr) {
    asm volatile("ldmatrix.sync.aligned.m8n8.x4.shared.b16 {%0,%1,%2,%3}, [%4];"
                 : "=r"(r[0]), "=r"(r[1]), "=r"(r[2]), "=r"(r[3]) : "r"(addr));
}
__device__ __forceinline__ void mma_f16(float* c, const uint32_t* a,
                                        const uint32_t* b) {
    asm volatile(
        "mma.sync.aligned.m16n8k16.row.col.f32.f16.f16.f32 "
        "{%0,%1,%2,%3}, {%4,%5,%6,%7}, {%8,%9}, {%0,%1,%2,%3};"
        : "+f"(c[0]), "+f"(c[1]), "+f"(c[2]), "+f"(c[3])
        : "r"(a[0]), "r"(a[1]), "r"(a[2]), "r"(a[3]), "r"(b[0]), "r"(b[1]));
}
#define CPA(sm, gp) \
    asm volatile("cp.async.cg.shared.global [%0], [%1], 16;" :: "r"(sm), "l"(gp))
#define CP_COMMIT() asm volatile("cp.async.commit_group;" ::: "memory")
#define CP_WAIT2()  asm volatile("cp.async.wait_group 2;" ::: "memory")

// ===================== small kernels ========================================
__global__ void zero_counts_kernel() {
    if (threadIdx.x < NE) g_count[threadIdx.x] = 0;
}

__global__ void gate_kernel(const float* __restrict__ x,
                            const float* __restrict__ gw) {
    int gtid = blockIdx.x * blockDim.x + threadIdx.x;
    int t = gtid >> 5;
    int lane = threadIdx.x & 31;
    if (t >= T_TOKENS) return;

    const float* xr = x + (size_t)t * DM;
    float acc[NE];
#pragma unroll
    for (int e = 0; e < NE; e++) acc[e] = 0.f;
    for (int d = lane; d < DM; d += 32) {
        float xv = xr[d];
#pragma unroll
        for (int e = 0; e < NE; e++) acc[e] += xv * gw[e * DM + d];
    }
#pragma unroll
    for (int e = 0; e < NE; e++)
#pragma unroll
        for (int o = 16; o > 0; o >>= 1)
            acc[e] += __shfl_xor_sync(0xffffffffu, acc[e], o);

    if (lane == 0) {
        float m = acc[0];
#pragma unroll
        for (int e = 1; e < NE; e++) m = fmaxf(m, acc[e]);
        float p[NE], s = 0.f;
#pragma unroll
        for (int e = 0; e < NE; e++) { p[e] = expf(acc[e] - m); s += p[e]; }
        float inv_s = 1.f / s;
#pragma unroll
        for (int e = 0; e < NE; e++) p[e] *= inv_s;
        int i0 = 0;
#pragma unroll
        for (int e = 1; e < NE; e++) if (p[e] > p[i0]) i0 = e;
        int i1 = (i0 == 0) ? 1 : 0;
#pragma unroll
        for (int e = 0; e < NE; e++)
            if (e != i0 && p[e] > p[i1]) i1 = e;
        float w0 = p[i0], w1 = p[i1];
        float inv = 1.f / (w0 + w1 + 1e-20f);
        w0 *= inv; w1 *= inv;
        int s0 = atomicAdd(&g_count[i0], 1);
        g_slot_token[i0 * MCAP + s0] = t;
        g_token_slot[t * 2 + 0] = i0 * MCAP + s0;
        g_token_w[t * 2 + 0] = w0;
        int s1 = atomicAdd(&g_count[i1], 1);
        g_slot_token[i1 * MCAP + s1] = t;
        g_token_slot[t * 2 + 1] = i1 * MCAP + s1;
        g_token_w[t * 2 + 1] = w1;
    }
}

// fp32 -> fp16, vectorized by 4
__global__ void tohalf_kernel(const float* __restrict__ src,
                              __half* __restrict__ dst, int n4) {
    int i = blockIdx.x * blockDim.x + threadIdx.x;
    if (i >= n4) return;
    float4 v = ((const float4*)src)[i];
    __half h0 = __float2half_rn(v.x);
    __half h1 = __float2half_rn(v.y);
    __half h2 = __float2half_rn(v.z);
    __half h3 = __float2half_rn(v.w);
    uint32_t p0 = ((uint32_t)__half_as_ushort(h1) << 16) | __half_as_ushort(h0);
    uint32_t p1 = ((uint32_t)__half_as_ushort(h3) << 16) | __half_as_ushort(h2);
    ((uint2*)dst)[i] = make_uint2(p0, p1);
}

__global__ void combine_kernel(float* __restrict__ out) {
    int t = blockIdx.x;
    int tid = threadIdx.x;
    int s0 = g_token_slot[t * 2 + 0];
    int s1 = g_token_slot[t * 2 + 1];
    float w0 = g_token_w[t * 2 + 0];
    float w1 = g_token_w[t * 2 + 1];
    const float4* e0 = (const float4*)(g_eo + (size_t)s0 * DM);
    const float4* e1 = (const float4*)(g_eo + (size_t)s1 * DM);
    float4* o = (float4*)(out + (size_t)t * DM);
    float4 a = e0[tid], b = e1[tid], c = o[tid];
    c.x += w0 * a.x + w1 * b.x;
    c.y += w0 * a.y + w1 * b.y;
    c.z += w0 * a.z + w1 * b.z;
    c.w += w0 * a.w + w1 * b.w;
    o[tid] = c;
}

// ===================== mma.sync GEMM ========================================
// C[M,N] = A[M,K] @ B[N,K]^T + bias. fp16 x fp16, fp32 accumulate.
// 128x256x32 block tile, 256 threads = 8 warps (2x4), warp tile 64x64.
// 4-stage cp.async pipeline, single __syncthreads per chunk.
#define BM 128
#define BN 256
#define BK 32
#define ROWB 80                          // bytes per smem row (64 used + 16 pad)
#define A_ARRB (128 * ROWB)              // 10240
#define B_ARRB (256 * ROWB)              // 20480
#define OFF_A 0
#define OFF_B A_ARRB
#define STAGEB (A_ARRB + B_ARRB)         // 30720
#define NSTAGE 4
#define SMEM_TOTAL_GEMM (NSTAGE * STAGEB) // 122880

__global__ void __launch_bounds__(256)
mma_gemm(const __half* __restrict__ Ah,
         const __half* __restrict__ Bw,
         const float* __restrict__ bias,
         float* __restrict__ Cf,
         __half* __restrict__ Chalf,
         const int* __restrict__ counts,
         const int* __restrict__ gather,
         int Mfixed, int N, int K,
         long long aStride,    // rows per expert in A (0 with gather)
         long long cStride,    // rows per expert in C
         int mode)             // 0: fp32 out; 1: relu + fp16 out
{
    const int e = blockIdx.z;
    const int M = counts ? counts[e] : Mfixed;
    const int row0 = blockIdx.x * BM;
    if (row0 >= M) return;
    const int col0 = blockIdx.y * BN;

    extern __shared__ char smem[];
    const uint32_t sb = smem_u32(smem);
    const int tid = threadIdx.x;
    const int wid = tid >> 5;
    const int lane = tid & 31;

    // ---- cp.async setup: 6 x 16B per thread per chunk ----------------------
    const int lrow = tid >> 2;          // 0..63
    const int seg = tid & 3;            // 16B segment within 64B row
    int ra0 = row0 + lrow, ra1 = row0 + 64 + lrow;
    int ca0 = (ra0 < M) ? ra0 : (M - 1);
    int ca1 = (ra1 < M) ? ra1 : (M - 1);
    long long ga0 = (long long)e * aStride +
                    (gather ? (long long)gather[(size_t)e * MCAP + ca0] : (long long)ca0);
    long long ga1 = (long long)e * aStride +
                    (gather ? (long long)gather[(size_t)e * MCAP + ca1] : (long long)ca1);

    const char* pA0 = (const char*)(Ah + (size_t)ga0 * K) + seg * 16;
    const char* pA1 = (const char*)(Ah + (size_t)ga1 * K) + seg * 16;
    const char* pB[4];   // B rows lrow+{0,64,128,192}
#pragma unroll
    for (int j = 0; j < 4; j++) {
        long long gb = (long long)e * N + col0 + lrow + j * 64;
        pB[j] = (const char*)(Bw + (size_t)gb * K) + seg * 16;
    }

    const uint32_t soA0 = lrow * ROWB + seg * 16;
    const uint32_t soA1 = (64 + lrow) * ROWB + seg * 16;

#define ISSUE(cc, st) do {                                                     \
    uint32_t _s = sb + (st) * STAGEB;                                          \
    size_t _g = (size_t)(cc) * 64;                                             \
    CPA(_s + OFF_A + soA0, pA0 + _g);                                          \
    CPA(_s + OFF_A + soA1, pA1 + _g);                                          \
    _Pragma("unroll")                                                          \
    for (int _j = 0; _j < 4; _j++)                                             \
        CPA(_s + OFF_B + (_j * 64 + lrow) * ROWB + seg * 16, pB[_j] + _g);     \
    CP_COMMIT();                                                               \
} while (0)

    // ---- fragment addressing ----------------------------------------------
    const int warp_m = wid >> 2;        // 0..1
    const int warp_n = wid & 3;         // 0..3
    const int arow = (lane & 7) + ((lane >> 3) & 1) * 8;
    const int akk = ((lane >> 4) & 1) * 8;
    const int brow = (lane & 7) + ((lane >> 4) & 1) * 8;
    const int bkk = ((lane >> 3) & 1) * 8;

    float acc[4][8][4];
#pragma unroll
    for (int mi = 0; mi < 4; mi++)
#pragma unroll
        for (int ni = 0; ni < 8; ni++)
#pragma unroll
            for (int q = 0; q < 4; q++) acc[mi][ni][q] = 0.f;

    const int NC = K / BK;
    ISSUE(0, 0);
    ISSUE(1, 1);
    ISSUE(2, 2);

    int st = 0, st_issue = 3;
    for (int c = 0; c < NC; c++) {
        CP_WAIT2();
        __syncthreads();
        if (c + 3 < NC) {
            ISSUE(c + 3, st_issue);
        } else {
            CP_COMMIT();               // keep wait_group invariant at tail
        }
        st_issue = (st_issue == NSTAGE - 1) ? 0 : st_issue + 1;

        const uint32_t sbase = sb + st * STAGEB;
#pragma unroll
        for (int ks = 0; ks < 2; ks++) {
            uint32_t afr[4][4], bfr[8][2];
#pragma unroll
            for (int mi = 0; mi < 4; mi++) {
                uint32_t ad = sbase + OFF_A +
                    (warp_m * 64 + mi * 16 + arow) * ROWB + (ks * 16 + akk) * 2;
                ldsm4(afr[mi], ad);
            }
#pragma unroll
            for (int np = 0; np < 4; np++) {
                uint32_t bd = sbase + OFF_B +
                    (warp_n * 64 + np * 16 + brow) * ROWB + (ks * 16 + bkk) * 2;
                uint32_t t0[4];
                ldsm4(t0, bd);
                bfr[np * 2][0] = t0[0]; bfr[np * 2][1] = t0[1];
                bfr[np * 2 + 1][0] = t0[2]; bfr[np * 2 + 1][1] = t0[3];
            }
#pragma unroll
            for (int mi = 0; mi < 4; mi++)
#pragma unroll
                for (int ni = 0; ni < 8; ni++)
                    mma_f16(acc[mi][ni], afr[mi], bfr[ni]);
        }
        st = (st == NSTAGE - 1) ? 0 : st + 1;
    }

    // ---- epilogue ----------------------------------------------------------
    const float* biasp = bias + (counts ? (size_t)e * N : 0);
    const int rin = lane >> 2;
    const int cpair = (lane & 3) * 2;

#pragma unroll
    for (int mi = 0; mi < 4; mi++) {
#pragma unroll
        for (int half = 0; half < 2; half++) {
            int rr = row0 + warp_m * 64 + mi * 16 + half * 8 + rin;
            if (rr >= M) continue;
            size_t crow = (size_t)e * cStride + rr;
#pragma unroll
            for (int ni = 0; ni < 8; ni++) {
                int col = col0 + warp_n * 64 + ni * 8 + cpair;
                float2 bv = *(const float2*)(biasp + col);
                float v0 = acc[mi][ni][half * 2 + 0] + bv.x;
                float v1 = acc[mi][ni][half * 2 + 1] + bv.y;
                if (mode) {
                    v0 = fmaxf(v0, 0.f);
                    v1 = fmaxf(v1, 0.f);
                    __half h0 = __float2half_rn(v0);
                    __half h1 = __float2half_rn(v1);
                    uint32_t hp = ((uint32_t)__half_as_ushort(h1) << 16) |
                                  __half_as_ushort(h0);
                    *(uint32_t*)(Chalf + crow * N + col) = hp;
                } else {
                    *(float2*)(Cf + crow * N + col) = make_float2(v0, v1);
                }
            }
        }
    }
#undef ISSUE
}

// ===================== host launch ==========================================
extern "C" void kernel_launch(void* const* d_in, const int* in_sizes, int n_in,
                              void* d_out, int out_size) {
    const float* x      = (const float*)d_in[0];
    const float* gate_w = (const float*)d_in[1];
    const float* w1     = (const float*)d_in[2];
    const float* b1     = (const float*)d_in[3];
    const float* w2     = (const float*)d_in[4];
    const float* b2     = (const float*)d_in[5];
    const float* ws1    = (const float*)d_in[6];
    const float* bs1    = (const float*)d_in[7];
    const float* ws2    = (const float*)d_in[8];
    const float* bs2    = (const float*)d_in[9];
    float* out = (float*)d_out;

    int *count_p, *slot_p;
    __half *xf, *w1f, *w2f, *ws1f, *ws2f, *hh, *hsh;
    float* eo;
    cudaGetSymbolAddress((void**)&count_p, g_count);
    cudaGetSymbolAddress((void**)&slot_p,  g_slot_token);
    cudaGetSymbolAddress((void**)&xf,  g_xf);
    cudaGetSymbolAddress((void**)&w1f, g_w1f);  cudaGetSymbolAddress((void**)&w2f, g_w2f);
    cudaGetSymbolAddress((void**)&ws1f, g_ws1f); cudaGetSymbolAddress((void**)&ws2f, g_ws2f);
    cudaGetSymbolAddress((void**)&hh,  g_hh);   cudaGetSymbolAddress((void**)&hsh, g_hsh);
    cudaGetSymbolAddress((void**)&eo,  g_eo);

    cudaFuncSetAttribute(mma_gemm, cudaFuncAttributeMaxDynamicSharedMemorySize,
                         SMEM_TOTAL_GEMM);

    zero_counts_kernel<<<1, 32>>>();
    gate_kernel<<<(T_TOKENS * 32) / 256, 256>>>(x, gate_w);
    {
        int n;
        n = T_TOKENS * DM; tohalf_kernel<<<n / 4 / 256, 256>>>(x,   xf,   n / 4);
        n = NE * DF * DM;  tohalf_kernel<<<n / 4 / 256, 256>>>(w1,  w1f,  n / 4);
        n = NE * DM * DF;  tohalf_kernel<<<n / 4 / 256, 256>>>(w2,  w2f,  n / 4);
        n = DF * DM;       tohalf_kernel<<<n / 4 / 256, 256>>>(ws1, ws1f, n / 4);
        n = DM * DF;       tohalf_kernel<<<n / 4 / 256, 256>>>(ws2, ws2f, n / 4);
    }
    // routed GEMM1: h = relu(x[gather] @ w1^T + b1) -> fp16
    {
        dim3 grid(MCAP / BM, DF / BN, NE);
        mma_gemm<<<grid, 256, SMEM_TOTAL_GEMM>>>(
            xf, w1f, b1, (float*)0, hh,
            count_p, slot_p, 0, DF, DM, 0LL, (long long)MCAP, 1);
    }
    // routed GEMM2: eo = h @ w2^T + b2 -> fp32
    {
        dim3 grid(MCAP / BM, DM / BN, NE);
        mma_gemm<<<grid, 256, SMEM_TOTAL_GEMM>>>(
            hh, w2f, b2, eo, (__half*)0,
            count_p, (const int*)0, 0, DM, DF,
            (long long)MCAP, (long long)MCAP, 0);
    }
    // shared GEMM1: hs = relu(x @ ws1^T + bs1) -> fp16
    {
        dim3 grid(T_TOKENS / BM, DF / BN, 1);
        mma_gemm<<<grid, 256, SMEM_TOTAL_GEMM>>>(
            xf, ws1f, bs1, (float*)0, hsh,
            (const int*)0, (const int*)0, T_TOKENS, DF, DM, 0LL, 0LL, 1);
    }
    // shared GEMM2: out = hs @ ws2^T + bs2 -> fp32 (initializes out)
    {
        dim3 grid(T_TOKENS / BM, DM / BN, 1);
        mma_gemm<<<grid, 256, SMEM_TOTAL_GEMM>>>(
            hsh, ws2f, bs2, out, (__half*)0,
            (const int*)0, (const int*)0, T_TOKENS, DM, DF, 0LL, 0LL, 0);
    }
    // combine routed into out
    combine_kernel<<<T_TOKENS, 256>>>(out);
}